// round 1
// baseline (speedup 1.0000x reference)
#include <cuda_runtime.h>
#include <math.h>
#include <stdint.h>

// ---------------------------------------------------------------------------
// MaxSA: block(7x7 window) attention + grid(32x32) attention, C=128, 4 heads.
// Round 0: straightforward fp32 implementation, tiled GEMMs, materialized
// attention scores in device scratch. Correctness first; roofline later.
// ---------------------------------------------------------------------------

#define CCH   128
#define HWDIM 224
#define MTOK  50176           // 224*224 tokens total per stage
#define NHEAD 4
#define HDIM  32

// ------------------------- device scratch ----------------------------------
__device__ float g_X  [MTOK * CCH];        //  25.7 MB  stage input (tokens)
__device__ float g_QKV[MTOK * 3 * CCH];    //  77  MB
__device__ float g_S  [49 * 4 * 1024 * 1024]; // 822 MB attention scores (worst case: grid)
__device__ float g_O  [MTOK * CCH];        //  attn output (pre-proj)
__device__ float g_Y  [MTOK * CCH];        //  post-proj + residual
__device__ float g_Yn [MTOK * CCH];        //  post-LN
__device__ float g_Z  [MTOK * 512];        //  102 MB   fc1 out
__device__ float g_Out[MTOK * CCH];        //  stage output (tokens)

// ------------------------- helpers -----------------------------------------
__device__ __forceinline__ float warp_red_max(float v) {
#pragma unroll
    for (int o = 16; o > 0; o >>= 1) v = fmaxf(v, __shfl_xor_sync(0xffffffffu, v, o));
    return v;
}
__device__ __forceinline__ float warp_red_sum(float v) {
#pragma unroll
    for (int o = 16; o > 0; o >>= 1) v += __shfl_xor_sync(0xffffffffu, v, o);
    return v;
}

// ------------------------- permutations ------------------------------------
// window_partition (7x7): X[(ho*32+wo), (hi*7+wi), c] = x[c, ho*7+hi, wo*7+wi]
__global__ void winpart_b_kernel(const float* __restrict__ x, float* __restrict__ X) {
    int idx = blockIdx.x * 256 + threadIdx.x;
    if (idx >= MTOK * CCH) return;
    int c   = idx & 127;
    int t   = idx >> 7;
    int tok = t % 49;
    int win = t / 49;
    int hi = tok / 7, wi = tok % 7;
    int ho = win >> 5, wo = win & 31;
    X[idx] = x[c * MTOK + (ho * 7 + hi) * HWDIM + wo * 7 + wi];
}

// unbind_b (quirky reshape) fused with window_partition(32x32).
// Out_b element (win_b=ho*32+wo, tok_b=hi*7+wi, c) lives at flat
// f = ((((c*32+ho)*7+hi)*7+wi)*32+wo) in the "buffer", which is re-viewed
// as (h2,w2,c2): f = (h2*224+w2)*128 + c2. Grid partition then reads
// T[c2, gho*32+ghi, gwo*32+gwi].
__global__ void permute_b2g_kernel(const float* __restrict__ A, float* __restrict__ Xg) {
    int idx = blockIdx.x * 256 + threadIdx.x;  // element of Xg [49,1024,128]
    if (idx >= MTOK * CCH) return;
    int cg  = idx & 127;
    int t   = idx >> 7;
    int tok = t & 1023;
    int win = t >> 10;
    int gho = win / 7, gwo = win % 7;
    int ghi = tok >> 5, gwi = tok & 31;
    int h2 = gho * 32 + ghi, w2 = gwo * 32 + gwi;
    int f = (h2 * HWDIM + w2) * CCH + cg;
    int wo = f & 31; f >>= 5;
    int wi = f % 7;  f /= 7;
    int hi = f % 7;  f /= 7;
    int ho = f & 31; f >>= 5;
    int c  = f;
    Xg[idx] = A[((ho * 32 + wo) * 49 + (hi * 7 + wi)) * CCH + c];
}

// unbind_g (quirky reshape) -> final NCHW output.
// buf2 flat f2 = ((((c*7+gho)*32+ghi)*32+gwi)*7+gwo), viewed as (h2,w2,c2).
__global__ void permute_g2out_kernel(const float* __restrict__ A, float* __restrict__ out) {
    int idx = blockIdx.x * 256 + threadIdx.x;  // element of out [128,224,224]
    if (idx >= MTOK * CCH) return;
    int w2 = idx % HWDIM;
    int t  = idx / HWDIM;
    int h2 = t % HWDIM;
    int c2 = t / HWDIM;
    int f = (h2 * HWDIM + w2) * CCH + c2;
    int gwo = f % 7;  f /= 7;
    int gwi = f & 31; f >>= 5;
    int ghi = f & 31; f >>= 5;
    int gho = f % 7;  f /= 7;
    int c   = f;
    out[idx] = A[((gho * 7 + gwo) * 1024 + ghi * 32 + gwi) * CCH + c];
}

// ------------------------- GEMM  C = A @ W^T (+bias)(+res) -----------------
// A: [M,K] row-major.  W: [N,K] row-major (torch Linear weight layout).
// Tiles: 64x64x16, 256 threads, 4x4 per thread. M,N div by 64; K div by 16.
__global__ void gemm_kernel(const float* __restrict__ A, const float* __restrict__ W,
                            const float* __restrict__ bias, const float* __restrict__ res,
                            float* __restrict__ Cout, int M, int N, int K) {
    __shared__ float As[16][65];
    __shared__ float Bs[16][65];
    int bm = blockIdx.x * 64;
    int bn = blockIdx.y * 64;
    int tid = threadIdx.x;
    int tx = tid & 15, ty = tid >> 4;
    float acc[4][4] = {};
    for (int k0 = 0; k0 < K; k0 += 16) {
#pragma unroll
        for (int i = tid; i < 64 * 16; i += 256) {
            int m = i >> 4, k = i & 15;
            As[k][m] = A[(size_t)(bm + m) * K + k0 + k];
        }
#pragma unroll
        for (int i = tid; i < 64 * 16; i += 256) {
            int n = i >> 4, k = i & 15;
            Bs[k][n] = W[(size_t)(bn + n) * K + k0 + k];
        }
        __syncthreads();
#pragma unroll
        for (int k = 0; k < 16; k++) {
            float a[4], bv[4];
#pragma unroll
            for (int i = 0; i < 4; i++) a[i] = As[k][ty * 4 + i];
#pragma unroll
            for (int j = 0; j < 4; j++) bv[j] = Bs[k][tx * 4 + j];
#pragma unroll
            for (int i = 0; i < 4; i++)
#pragma unroll
                for (int j = 0; j < 4; j++) acc[i][j] += a[i] * bv[j];
        }
        __syncthreads();
    }
#pragma unroll
    for (int i = 0; i < 4; i++) {
        int m = bm + ty * 4 + i;
#pragma unroll
        for (int j = 0; j < 4; j++) {
            int n = bn + tx * 4 + j;
            float v = acc[i][j];
            if (bias) v += bias[n];
            size_t o = (size_t)m * N + n;
            if (res) v += res[o];
            Cout[o] = v;
        }
    }
}

// ------------------------- attention scores --------------------------------
// S[bh,n,m] = sqrt(32) * <q_n, k_m> + table[relidx(n,m)*4 + h]
// QKV layout: [B, N, 3*128] with col = which*128 + h*32 + d.
__global__ void attn_score_kernel(const float* __restrict__ QKV,
                                  const float* __restrict__ table,
                                  float* __restrict__ S, int N, int win) {
    int bh = blockIdx.z;
    int b = bh >> 2, h = bh & 3;
    int bn = blockIdx.x * 64;
    int bm = blockIdx.y * 64;
    __shared__ float Qs[32][65];
    __shared__ float Ks[32][65];
    int tid = threadIdx.x;
    const size_t base = (size_t)b * N * 384;
#pragma unroll
    for (int i = tid; i < 64 * 32; i += 256) {
        int r = i >> 5, d = i & 31;
        int n = bn + r;
        Qs[d][r] = (n < N) ? QKV[base + (size_t)n * 384 + h * 32 + d] : 0.f;
        int m = bm + r;
        Ks[d][r] = (m < N) ? QKV[base + (size_t)m * 384 + 128 + h * 32 + d] : 0.f;
    }
    __syncthreads();
    int tx = tid & 15, ty = tid >> 4;
    float acc[4][4] = {};
#pragma unroll
    for (int d = 0; d < 32; d++) {
        float a[4], bv[4];
#pragma unroll
        for (int i = 0; i < 4; i++) a[i] = Qs[d][ty * 4 + i];
#pragma unroll
        for (int j = 0; j < 4; j++) bv[j] = Ks[d][tx * 4 + j];
#pragma unroll
        for (int i = 0; i < 4; i++)
#pragma unroll
            for (int j = 0; j < 4; j++) acc[i][j] += a[i] * bv[j];
    }
    const float scale = 5.656854249492381f;   // sqrt(head_dim) -- faithful quirk
    int W2 = 2 * win - 1;
#pragma unroll
    for (int i = 0; i < 4; i++) {
        int n = bn + ty * 4 + i;
        if (n >= N) continue;
        int i1 = n / win, j1 = n % win;
#pragma unroll
        for (int j = 0; j < 4; j++) {
            int m = bm + tx * 4 + j;
            if (m >= N) continue;
            int i2 = m / win, j2 = m % win;
            int ridx = (i1 - i2 + win - 1) * W2 + (j1 - j2 + win - 1);
            S[((size_t)bh * N + n) * N + m] = acc[i][j] * scale + table[ridx * 4 + h];
        }
    }
}

// ------------------------- softmax over rows -------------------------------
__global__ void softmax_kernel(float* __restrict__ S, int N) {
    size_t row = blockIdx.x;
    float* p = S + row * (size_t)N;
    int tid = threadIdx.x;  // 128
    __shared__ float sb[4];
    __shared__ float sb2[4];
    float mx = -1e30f;
    for (int i = tid; i < N; i += 128) mx = fmaxf(mx, p[i]);
    mx = warp_red_max(mx);
    if ((tid & 31) == 0) sb[tid >> 5] = mx;
    __syncthreads();
    mx = fmaxf(fmaxf(sb[0], sb[1]), fmaxf(sb[2], sb[3]));
    float s = 0.f;
    for (int i = tid; i < N; i += 128) {
        float e = __expf(p[i] - mx);
        p[i] = e;
        s += e;
    }
    s = warp_red_sum(s);
    if ((tid & 31) == 0) sb2[tid >> 5] = s;
    __syncthreads();
    s = sb2[0] + sb2[1] + sb2[2] + sb2[3];
    float inv = 1.0f / s;
    for (int i = tid; i < N; i += 128) p[i] *= inv;
}

// ------------------------- O = P @ V ---------------------------------------
// O[b, n, h*32+d] = sum_m P[bh,n,m] * V[b,m,h,d]
__global__ void attn_out_kernel(const float* __restrict__ P, const float* __restrict__ QKV,
                                float* __restrict__ O, int N) {
    int bh = blockIdx.z;
    int b = bh >> 2, h = bh & 3;
    int bn = blockIdx.x * 64;
    __shared__ float Ps[32][65];   // [m][n]
    __shared__ float Vs[32][33];   // [m][d]
    int tid = threadIdx.x;  // 256
    float acc[2][4] = {};
    const size_t pbase = (size_t)bh * N * N;
    const size_t vbase = (size_t)b * N * 384 + 256 + h * 32;
    for (int m0 = 0; m0 < N; m0 += 32) {
#pragma unroll
        for (int i = tid; i < 64 * 32; i += 256) {
            int r = i >> 5, mm = i & 31;
            int n = bn + r, m = m0 + mm;
            Ps[mm][r] = (n < N && m < N) ? P[pbase + (size_t)n * N + m] : 0.f;
        }
#pragma unroll
        for (int i = tid; i < 32 * 32; i += 256) {
            int mm = i >> 5, d = i & 31;
            int m = m0 + mm;
            Vs[mm][d] = (m < N) ? QKV[vbase + (size_t)m * 384 + d] : 0.f;
        }
        __syncthreads();
        int tx = tid & 7, ty = tid >> 3;
#pragma unroll
        for (int mm = 0; mm < 32; mm++) {
            float a0 = Ps[mm][ty * 2 + 0];
            float a1 = Ps[mm][ty * 2 + 1];
            float bv[4];
#pragma unroll
            for (int j = 0; j < 4; j++) bv[j] = Vs[mm][tx * 4 + j];
#pragma unroll
            for (int j = 0; j < 4; j++) {
                acc[0][j] += a0 * bv[j];
                acc[1][j] += a1 * bv[j];
            }
        }
        __syncthreads();
    }
    int tx = tid & 7, ty = tid >> 3;
#pragma unroll
    for (int i = 0; i < 2; i++) {
        int n = bn + ty * 2 + i;
        if (n >= N) continue;
#pragma unroll
        for (int j = 0; j < 4; j++) {
            O[((size_t)b * N + n) * CCH + h * 32 + tx * 4 + j] = acc[i][j];
        }
    }
}

// ------------------------- LayerNorm (D=128) -------------------------------
__global__ void ln_kernel(const float* __restrict__ Y, const float* __restrict__ g,
                          const float* __restrict__ bta, float* __restrict__ out) {
    size_t row = blockIdx.x;
    int tid = threadIdx.x;  // 128
    __shared__ float sb[4];
    __shared__ float sb2[4];
    float v = Y[row * CCH + tid];
    float s = warp_red_sum(v);
    if ((tid & 31) == 0) sb[tid >> 5] = s;
    __syncthreads();
    float mu = (sb[0] + sb[1] + sb[2] + sb[3]) * (1.0f / 128.0f);
    float d = v - mu;
    float s2 = warp_red_sum(d * d);
    if ((tid & 31) == 0) sb2[tid >> 5] = s2;
    __syncthreads();
    float var = (sb2[0] + sb2[1] + sb2[2] + sb2[3]) * (1.0f / 128.0f);
    float r = rsqrtf(var + 1e-5f);
    out[row * CCH + tid] = d * r * g[tid] + bta[tid];
}

// ------------------------- stage orchestration -----------------------------
static void run_stage(const float* const* p, float* X, float* QKV, float* S,
                      float* O, float* Y, float* Yn, float* Z, float* Out,
                      int B, int N, int win) {
    const float* table  = p[0];
    const float* qkv_w  = p[1];
    const float* proj_w = p[2];
    const float* proj_b = p[3];
    const float* ln_g   = p[4];
    const float* ln_b   = p[5];
    const float* fc1_w  = p[6];
    const float* fc1_b  = p[7];
    const float* fc2_w  = p[8];
    const float* fc2_b  = p[9];
    int M = B * N;  // 50176 in both stages
    int nt = (N + 63) / 64;

    gemm_kernel<<<dim3(M / 64, 384 / 64), 256>>>(X, qkv_w, nullptr, nullptr, QKV, M, 384, 128);
    attn_score_kernel<<<dim3(nt, nt, B * NHEAD), 256>>>(QKV, table, S, N, win);
    softmax_kernel<<<B * NHEAD * N, 128>>>(S, N);
    attn_out_kernel<<<dim3(nt, 1, B * NHEAD), 256>>>(S, QKV, O, N);
    gemm_kernel<<<dim3(M / 64, 128 / 64), 256>>>(O, proj_w, proj_b, X, Y, M, 128, 128);
    ln_kernel<<<M, 128>>>(Y, ln_g, ln_b, Yn);
    gemm_kernel<<<dim3(M / 64, 512 / 64), 256>>>(Yn, fc1_w, fc1_b, nullptr, Z, M, 512, 128);
    gemm_kernel<<<dim3(M / 64, 128 / 64), 256>>>(Z, fc2_w, fc2_b, Yn, Out, M, 128, 512);
}

extern "C" void kernel_launch(void* const* d_in, const int* in_sizes, int n_in,
                              void* d_out, int out_size) {
    const float* x = (const float*)d_in[0];
    const float* bp[10];
    const float* gp[10];
    for (int i = 0; i < 10; i++) bp[i] = (const float*)d_in[1 + i];
    for (int i = 0; i < 10; i++) gp[i] = (const float*)d_in[11 + i];

    float *X, *QKV, *S, *O, *Y, *Yn, *Z, *Out;
    cudaGetSymbolAddress((void**)&X,   g_X);
    cudaGetSymbolAddress((void**)&QKV, g_QKV);
    cudaGetSymbolAddress((void**)&S,   g_S);
    cudaGetSymbolAddress((void**)&O,   g_O);
    cudaGetSymbolAddress((void**)&Y,   g_Y);
    cudaGetSymbolAddress((void**)&Yn,  g_Yn);
    cudaGetSymbolAddress((void**)&Z,   g_Z);
    cudaGetSymbolAddress((void**)&Out, g_Out);

    const int nblk = (MTOK * CCH + 255) / 256;  // 25088

    // Stage 1: 7x7 block attention (B=1024 windows, N=49 tokens)
    winpart_b_kernel<<<nblk, 256>>>(x, X);
    run_stage(bp, X, QKV, S, O, Y, Yn, Z, Out, 1024, 49, 7);

    // Permute: unbind_b (quirky) + grid partition -> Xg [49, 1024, 128]
    permute_b2g_kernel<<<nblk, 256>>>(Out, X);

    // Stage 2: 32x32 grid attention (B=49 windows, N=1024 tokens)
    run_stage(gp, X, QKV, S, O, Y, Yn, Z, Out, 49, 1024, 32);

    // Final: unbind_g (quirky) -> NCHW output
    permute_g2out_kernel<<<nblk, 256>>>(Out, (float*)d_out);
}

// round 3
// speedup vs baseline: 2.0099x; 2.0099x over previous
#include <cuda_runtime.h>
#include <cuda_bf16.h>
#include <math.h>
#include <stdint.h>

// ---------------------------------------------------------------------------
// MaxSA R2: all big matmuls via mma.sync bf16 (hi/lo split, 3 passes) since
// the build targets plain sm_103 (no tcgen05). Stage1 (7x7) attention fp32.
// ---------------------------------------------------------------------------

#define CCH   128
#define HWDIM 224
#define MTOK  50176
#define NHEAD 4

__device__ float g_X  [MTOK * CCH];
__device__ float g_QKV[MTOK * 3 * CCH];
__device__ float g_S  [49 * 4 * 1024 * 1024];   // 822 MB (stage2 scores)
__device__ float g_O  [MTOK * CCH];
__device__ float g_Y  [MTOK * CCH];
__device__ float g_Yn [MTOK * CCH];
__device__ float g_Z  [MTOK * 512];
__device__ float g_Out[MTOK * CCH];

// ------------------------- helpers -----------------------------------------
__device__ __forceinline__ float warp_red_max(float v) {
#pragma unroll
    for (int o = 16; o > 0; o >>= 1) v = fmaxf(v, __shfl_xor_sync(0xffffffffu, v, o));
    return v;
}
__device__ __forceinline__ float warp_red_sum(float v) {
#pragma unroll
    for (int o = 16; o > 0; o >>= 1) v += __shfl_xor_sync(0xffffffffu, v, o);
    return v;
}
__device__ __forceinline__ uint32_t smem_u32(const void* p) {
    uint32_t a;
    asm("{ .reg .u64 t; cvta.to.shared.u64 t, %1; cvt.u32.u64 %0, t; }" : "=r"(a) : "l"(p));
    return a;
}
__device__ __forceinline__ void mma_bf16(float* c, const uint32_t* a, const uint32_t* b) {
    asm volatile(
        "mma.sync.aligned.m16n8k16.row.col.f32.bf16.bf16.f32 "
        "{%0,%1,%2,%3}, {%4,%5,%6,%7}, {%8,%9}, {%0,%1,%2,%3};"
        : "+f"(c[0]), "+f"(c[1]), "+f"(c[2]), "+f"(c[3])
        : "r"(a[0]), "r"(a[1]), "r"(a[2]), "r"(a[3]), "r"(b[0]), "r"(b[1]));
}
__device__ __forceinline__ void ldm_x4(uint32_t* r, uint32_t addr) {
    asm volatile("ldmatrix.sync.aligned.m8n8.x4.shared.b16 {%0,%1,%2,%3}, [%4];"
                 : "=r"(r[0]), "=r"(r[1]), "=r"(r[2]), "=r"(r[3]) : "r"(addr));
}
__device__ __forceinline__ void ldm_x2(uint32_t* r, uint32_t addr) {
    asm volatile("ldmatrix.sync.aligned.m8n8.x2.shared.b16 {%0,%1}, [%2];"
                 : "=r"(r[0]), "=r"(r[1]) : "r"(addr));
}
__device__ __forceinline__ uint32_t pack_hi(float x, float y) {
    return (uint32_t)__bfloat16_as_ushort(__float2bfloat16(x)) |
           ((uint32_t)__bfloat16_as_ushort(__float2bfloat16(y)) << 16);
}
__device__ __forceinline__ uint32_t pack_lo(float x, float y) {
    float xh = __bfloat162float(__float2bfloat16(x));
    float yh = __bfloat162float(__float2bfloat16(y));
    return (uint32_t)__bfloat16_as_ushort(__float2bfloat16(x - xh)) |
           ((uint32_t)__bfloat16_as_ushort(__float2bfloat16(y - yh)) << 16);
}

// ---------------------------------------------------------------------------
// mma.sync GEMM: C tile [128x64] = A @ B^T, bf16 hi/lo split (3 passes).
// A: [M,K] row-major (lda). B: [Nb,K] row-major (ldb), or [K,Nb] if transB.
// Batch: base + (z>>2)*Sb + (z&3)*Sh.
// mode 0: dense (+bias,+res). mode 1: score (*sqrt32 + relpos). mode 2: plain.
// Requires K % 32 == 0, M % 128 == 0.
// ---------------------------------------------------------------------------
#define RS 40   // smem row stride in bf16 elements (80 bytes)

__global__ void __launch_bounds__(256)
gemm_mma(const float* __restrict__ A, long long lda, long long aSb, long long aSh,
         const float* __restrict__ B, long long ldb, long long bSb, long long bSh,
         float* __restrict__ C, long long ldc, long long cSb, long long cSh,
         int K, int NtotB, int transB, int mode,
         const float* __restrict__ bias, const float* __restrict__ res,
         const float* __restrict__ table, int win) {
    __shared__ __align__(16) unsigned short Ah[128 * RS];
    __shared__ __align__(16) unsigned short Al[128 * RS];
    __shared__ __align__(16) unsigned short Bh[64 * RS];
    __shared__ __align__(16) unsigned short Bl[64 * RS];

    int tid = threadIdx.x, wid = tid >> 5, l = tid & 31;
    int z = blockIdx.z, zb = z >> 2, zh = z & 3;
    A += (size_t)zb * aSb + (size_t)zh * aSh;
    B += (size_t)zb * bSb + (size_t)zh * bSh;
    C += (size_t)zb * cSb + (size_t)zh * cSh;
    long long bm = (long long)blockIdx.x * 128;
    int bn = blockIdx.y * 64;
    int wm = (wid >> 1) * 32, wn = (wid & 1) * 32;

    uint32_t uAh = smem_u32(Ah), uAl = smem_u32(Al);
    uint32_t uBh = smem_u32(Bh), uBl = smem_u32(Bl);

    float acc[2][4][4];
#pragma unroll
    for (int i = 0; i < 2; i++)
#pragma unroll
        for (int j = 0; j < 4; j++)
#pragma unroll
            for (int k = 0; k < 4; k++) acc[i][j][k] = 0.f;

    for (int k0 = 0; k0 < K; k0 += 32) {
        // ---- A tile: 128 rows x 32 k ----
#pragma unroll
        for (int s = tid; s < 1024; s += 256) {
            int row = s >> 3, kq = s & 7;
            const float* p = A + (bm + row) * lda + k0 + kq * 4;
            float4 u = *(const float4*)p;
            uint2 h = make_uint2(pack_hi(u.x, u.y), pack_hi(u.z, u.w));
            uint2 lo = make_uint2(pack_lo(u.x, u.y), pack_lo(u.z, u.w));
            *(uint2*)(Ah + row * RS + kq * 4) = h;
            *(uint2*)(Al + row * RS + kq * 4) = lo;
        }
        // ---- B tile: 64 rows x 32 k ----
        if (!transB) {
#pragma unroll
            for (int s = tid; s < 512; s += 256) {
                int row = s >> 3, kq = s & 7;
                float4 u = make_float4(0.f, 0.f, 0.f, 0.f);
                if (bn + row < NtotB)
                    u = *(const float4*)(B + (size_t)(bn + row) * ldb + k0 + kq * 4);
                *(uint2*)(Bh + row * RS + kq * 4) = make_uint2(pack_hi(u.x, u.y), pack_hi(u.z, u.w));
                *(uint2*)(Bl + row * RS + kq * 4) = make_uint2(pack_lo(u.x, u.y), pack_lo(u.z, u.w));
            }
        } else {
#pragma unroll
            for (int s = tid; s < 512; s += 256) {
                int kk = s >> 4, nq = (s & 15) * 4;
                float4 u = make_float4(0.f, 0.f, 0.f, 0.f);
                if (bn + nq + 3 < NtotB)
                    u = *(const float4*)(B + (size_t)(k0 + kk) * ldb + bn + nq);
                float v[4] = {u.x, u.y, u.z, u.w};
#pragma unroll
                for (int j = 0; j < 4; j++) {
                    float hi = __bfloat162float(__float2bfloat16(v[j]));
                    Bh[(nq + j) * RS + kk] = __bfloat16_as_ushort(__float2bfloat16(v[j]));
                    Bl[(nq + j) * RS + kk] = __bfloat16_as_ushort(__float2bfloat16(v[j] - hi));
                }
            }
        }
        __syncthreads();
        // ---- MMA: 2 k16 steps ----
#pragma unroll
        for (int s2 = 0; s2 < 2; s2++) {
            int ks = s2 * 16;
            uint32_t ah[2][4], al[2][4], bh[4][2], bl[4][2];
            uint32_t aoff = (uint32_t)((wm + (l & 15)) * RS + ks + (l >> 4) * 8) * 2;
            ldm_x4(ah[0], uAh + aoff);
            ldm_x4(al[0], uAl + aoff);
            ldm_x4(ah[1], uAh + aoff + 16 * RS * 2);
            ldm_x4(al[1], uAl + aoff + 16 * RS * 2);
            uint32_t boff = (uint32_t)((wn + (l & 7)) * RS + ks + ((l >> 3) & 1) * 8) * 2;
#pragma unroll
            for (int ni = 0; ni < 4; ni++) {
                ldm_x2(bh[ni], uBh + boff + ni * 8 * RS * 2);
                ldm_x2(bl[ni], uBl + boff + ni * 8 * RS * 2);
            }
#pragma unroll
            for (int mi = 0; mi < 2; mi++)
#pragma unroll
                for (int ni = 0; ni < 4; ni++) {
                    mma_bf16(acc[mi][ni], ah[mi], bh[ni]);
                    mma_bf16(acc[mi][ni], ah[mi], bl[ni]);
                    mma_bf16(acc[mi][ni], al[mi], bh[ni]);
                }
        }
        __syncthreads();
    }

    // ---- epilogue ----
    int r0 = (int)(wm + (l >> 2));
    int cbase = wn + (l & 3) * 2;
    if (mode == 0) {
#pragma unroll
        for (int mi = 0; mi < 2; mi++) {
#pragma unroll
            for (int half = 0; half < 2; half++) {
                long long row = bm + r0 + mi * 16 + half * 8;
#pragma unroll
                for (int ni = 0; ni < 4; ni++) {
                    int col = bn + cbase + ni * 8;
                    float v0 = acc[mi][ni][half * 2 + 0];
                    float v1 = acc[mi][ni][half * 2 + 1];
                    if (bias) { v0 += bias[col]; v1 += bias[col + 1]; }
                    size_t o = (size_t)row * ldc + col;
                    if (res) { v0 += res[o]; v1 += res[o + 1]; }
                    *(float2*)(C + o) = make_float2(v0, v1);
                }
            }
        }
    } else if (mode == 1) {
        const float sc = 5.656854249492381f;
        int W2 = 2 * win - 1;
#pragma unroll
        for (int mi = 0; mi < 2; mi++) {
#pragma unroll
            for (int half = 0; half < 2; half++) {
                int n = (int)(bm + r0 + mi * 16 + half * 8);
                int i1 = n / win, j1 = n % win;
#pragma unroll
                for (int ni = 0; ni < 4; ni++) {
                    int col = bn + cbase + ni * 8;
                    int i2a = col / win, j2a = col % win;
                    int i2b = (col + 1) / win, j2b = (col + 1) % win;
                    int ra = (i1 - i2a + win - 1) * W2 + (j1 - j2a + win - 1);
                    int rb = (i1 - i2b + win - 1) * W2 + (j1 - j2b + win - 1);
                    float v0 = acc[mi][ni][half * 2 + 0] * sc + table[ra * 4 + zh];
                    float v1 = acc[mi][ni][half * 2 + 1] * sc + table[rb * 4 + zh];
                    *(float2*)(C + (size_t)n * ldc + col) = make_float2(v0, v1);
                }
            }
        }
    } else {
#pragma unroll
        for (int mi = 0; mi < 2; mi++) {
#pragma unroll
            for (int half = 0; half < 2; half++) {
                long long row = bm + r0 + mi * 16 + half * 8;
#pragma unroll
                for (int ni = 0; ni < 4; ni++) {
                    int col = bn + cbase + ni * 8;
                    if (col + 1 < NtotB) {
                        *(float2*)(C + (size_t)row * ldc + col) =
                            make_float2(acc[mi][ni][half * 2], acc[mi][ni][half * 2 + 1]);
                    }
                }
            }
        }
    }
}

// ------------------------- permutations ------------------------------------
__global__ void winpart_b_kernel(const float* __restrict__ x, float* __restrict__ X) {
    int idx = blockIdx.x * 256 + threadIdx.x;
    if (idx >= MTOK * CCH) return;
    int c = idx & 127;
    int t = idx >> 7;
    int tok = t % 49;
    int win = t / 49;
    int hi = tok / 7, wi = tok % 7;
    int ho = win >> 5, wo = win & 31;
    X[idx] = x[c * MTOK + (ho * 7 + hi) * HWDIM + wo * 7 + wi];
}
__global__ void permute_b2g_kernel(const float* __restrict__ A, float* __restrict__ Xg) {
    int idx = blockIdx.x * 256 + threadIdx.x;
    if (idx >= MTOK * CCH) return;
    int cg = idx & 127;
    int t = idx >> 7;
    int tok = t & 1023;
    int win = t >> 10;
    int gho = win / 7, gwo = win % 7;
    int ghi = tok >> 5, gwi = tok & 31;
    int h2 = gho * 32 + ghi, w2 = gwo * 32 + gwi;
    int f = (h2 * HWDIM + w2) * CCH + cg;
    int wo = f & 31; f >>= 5;
    int wi = f % 7;  f /= 7;
    int hi = f % 7;  f /= 7;
    int ho = f & 31; f >>= 5;
    int c = f;
    Xg[idx] = A[((ho * 32 + wo) * 49 + (hi * 7 + wi)) * CCH + c];
}
__global__ void permute_g2out_kernel(const float* __restrict__ A, float* __restrict__ out) {
    int idx = blockIdx.x * 256 + threadIdx.x;
    if (idx >= MTOK * CCH) return;
    int w2 = idx % HWDIM;
    int t = idx / HWDIM;
    int h2 = t % HWDIM;
    int c2 = t / HWDIM;
    int f = (h2 * HWDIM + w2) * CCH + c2;
    int gwo = f % 7;  f /= 7;
    int gwi = f & 31; f >>= 5;
    int ghi = f & 31; f >>= 5;
    int gho = f % 7;  f /= 7;
    int c = f;
    out[idx] = A[((gho * 7 + gwo) * 1024 + ghi * 32 + gwi) * CCH + c];
}

// ------------------------- stage1 fp32 attention ----------------------------
__global__ void attn_score_kernel(const float* __restrict__ QKV,
                                  const float* __restrict__ table,
                                  float* __restrict__ S, int N, int win) {
    int bh = blockIdx.z;
    int b = bh >> 2, h = bh & 3;
    int bn = blockIdx.x * 64;
    int bm = blockIdx.y * 64;
    __shared__ float Qs[32][65];
    __shared__ float Ks[32][65];
    int tid = threadIdx.x;
    const size_t base = (size_t)b * N * 384;
#pragma unroll
    for (int i = tid; i < 64 * 32; i += 256) {
        int r = i >> 5, d = i & 31;
        int n = bn + r;
        Qs[d][r] = (n < N) ? QKV[base + (size_t)n * 384 + h * 32 + d] : 0.f;
        int m = bm + r;
        Ks[d][r] = (m < N) ? QKV[base + (size_t)m * 384 + 128 + h * 32 + d] : 0.f;
    }
    __syncthreads();
    int tx = tid & 15, ty = tid >> 4;
    float acc[4][4] = {};
#pragma unroll
    for (int d = 0; d < 32; d++) {
        float a[4], bv[4];
#pragma unroll
        for (int i = 0; i < 4; i++) a[i] = Qs[d][ty * 4 + i];
#pragma unroll
        for (int j = 0; j < 4; j++) bv[j] = Ks[d][tx * 4 + j];
#pragma unroll
        for (int i = 0; i < 4; i++)
#pragma unroll
            for (int j = 0; j < 4; j++) acc[i][j] += a[i] * bv[j];
    }
    const float scale = 5.656854249492381f;
    int W2 = 2 * win - 1;
#pragma unroll
    for (int i = 0; i < 4; i++) {
        int n = bn + ty * 4 + i;
        if (n >= N) continue;
        int i1 = n / win, j1 = n % win;
#pragma unroll
        for (int j = 0; j < 4; j++) {
            int m = bm + tx * 4 + j;
            if (m >= N) continue;
            int i2 = m / win, j2 = m % win;
            int ridx = (i1 - i2 + win - 1) * W2 + (j1 - j2 + win - 1);
            S[((size_t)bh * N + n) * N + m] = acc[i][j] * scale + table[ridx * 4 + h];
        }
    }
}
// softmax: one warp per row (good for small and large N)
__global__ void softmax_warp_kernel(float* __restrict__ S, int N, long long nrows) {
    long long row = (long long)blockIdx.x * 4 + (threadIdx.x >> 5);
    if (row >= nrows) return;
    int lane = threadIdx.x & 31;
    float* p = S + row * (size_t)N;
    float mx = -1e30f;
    for (int i = lane; i < N; i += 32) mx = fmaxf(mx, p[i]);
    mx = warp_red_max(mx);
    float s = 0.f;
    for (int i = lane; i < N; i += 32) {
        float e = __expf(p[i] - mx);
        p[i] = e;
        s += e;
    }
    s = warp_red_sum(s);
    float inv = 1.0f / s;
    for (int i = lane; i < N; i += 32) p[i] *= inv;
}
__global__ void attn_out_kernel(const float* __restrict__ P, const float* __restrict__ QKV,
                                float* __restrict__ O, int N) {
    int bh = blockIdx.z;
    int b = bh >> 2, h = bh & 3;
    int bn = blockIdx.x * 64;
    __shared__ float Ps[32][65];
    __shared__ float Vs[32][33];
    int tid = threadIdx.x;
    float acc[2][4] = {};
    const size_t pbase = (size_t)bh * N * N;
    const size_t vbase = (size_t)b * N * 384 + 256 + h * 32;
    for (int m0 = 0; m0 < N; m0 += 32) {
#pragma unroll
        for (int i = tid; i < 64 * 32; i += 256) {
            int r = i >> 5, mm = i & 31;
            int n = bn + r, m = m0 + mm;
            Ps[mm][r] = (n < N && m < N) ? P[pbase + (size_t)n * N + m] : 0.f;
        }
#pragma unroll
        for (int i = tid; i < 32 * 32; i += 256) {
            int mm = i >> 5, d = i & 31;
            int m = m0 + mm;
            Vs[mm][d] = (m < N) ? QKV[vbase + (size_t)m * 384 + d] : 0.f;
        }
        __syncthreads();
        int tx = tid & 7, ty = tid >> 3;
#pragma unroll
        for (int mm = 0; mm < 32; mm++) {
            float a0 = Ps[mm][ty * 2 + 0];
            float a1 = Ps[mm][ty * 2 + 1];
            float bv[4];
#pragma unroll
            for (int j = 0; j < 4; j++) bv[j] = Vs[mm][tx * 4 + j];
#pragma unroll
            for (int j = 0; j < 4; j++) {
                acc[0][j] += a0 * bv[j];
                acc[1][j] += a1 * bv[j];
            }
        }
        __syncthreads();
    }
    int tx = tid & 7, ty = tid >> 3;
#pragma unroll
    for (int i = 0; i < 2; i++) {
        int n = bn + ty * 2 + i;
        if (n >= N) continue;
#pragma unroll
        for (int j = 0; j < 4; j++) {
            O[((size_t)b * N + n) * CCH + h * 32 + tx * 4 + j] = acc[i][j];
        }
    }
}
__global__ void ln_kernel(const float* __restrict__ Y, const float* __restrict__ g,
                          const float* __restrict__ bta, float* __restrict__ out) {
    size_t row = blockIdx.x;
    int tid = threadIdx.x;
    __shared__ float sb[4];
    __shared__ float sb2[4];
    float v = Y[row * CCH + tid];
    float s = warp_red_sum(v);
    if ((tid & 31) == 0) sb[tid >> 5] = s;
    __syncthreads();
    float mu = (sb[0] + sb[1] + sb[2] + sb[3]) * (1.0f / 128.0f);
    float d = v - mu;
    float s2 = warp_red_sum(d * d);
    if ((tid & 31) == 0) sb2[tid >> 5] = s2;
    __syncthreads();
    float var = (sb2[0] + sb2[1] + sb2[2] + sb2[3]) * (1.0f / 128.0f);
    float r = rsqrtf(var + 1e-5f);
    out[row * CCH + tid] = d * r * g[tid] + bta[tid];
}

// ------------------------- host orchestration -------------------------------
static void launch_dense(const float* A, int lda, const float* W,
                         const float* bias, const float* res,
                         float* C, int N, int K) {
    gemm_mma<<<dim3(MTOK / 128, N / 64, 1), 256>>>(
        A, lda, 0, 0, W, K, 0, 0, C, N, 0, 0,
        K, N, 0, 0, bias, res, nullptr, 0);
}

extern "C" void kernel_launch(void* const* d_in, const int* in_sizes, int n_in,
                              void* d_out, int out_size) {
    const float* x = (const float*)d_in[0];
    const float* bp[10];
    const float* gp[10];
    for (int i = 0; i < 10; i++) bp[i] = (const float*)d_in[1 + i];
    for (int i = 0; i < 10; i++) gp[i] = (const float*)d_in[11 + i];

    float *X, *QKV, *S, *O, *Y, *Yn, *Z, *Out;
    cudaGetSymbolAddress((void**)&X, g_X);
    cudaGetSymbolAddress((void**)&QKV, g_QKV);
    cudaGetSymbolAddress((void**)&S, g_S);
    cudaGetSymbolAddress((void**)&O, g_O);
    cudaGetSymbolAddress((void**)&Y, g_Y);
    cudaGetSymbolAddress((void**)&Yn, g_Yn);
    cudaGetSymbolAddress((void**)&Z, g_Z);
    cudaGetSymbolAddress((void**)&Out, g_Out);

    const int nblk = (MTOK * CCH + 255) / 256;

    // ================= Stage 1: 7x7 windows (B=1024, N=49) ==================
    winpart_b_kernel<<<nblk, 256>>>(x, X);
    launch_dense(X, 128, bp[1], nullptr, nullptr, QKV, 384, 128);
    attn_score_kernel<<<dim3(1, 1, 4096), 256>>>(QKV, bp[0], S, 49, 7);
    softmax_warp_kernel<<<(4096LL * 49 + 3) / 4, 128>>>(S, 49, 4096LL * 49);
    attn_out_kernel<<<dim3(1, 1, 4096), 256>>>(S, QKV, O, 49);
    launch_dense(O, 128, bp[2], bp[3], X, Y, 128, 128);
    ln_kernel<<<MTOK, 128>>>(Y, bp[4], bp[5], Yn);
    launch_dense(Yn, 128, bp[6], bp[7], nullptr, Z, 512, 128);
    launch_dense(Z, 512, bp[8], bp[9], Yn, Out, 128, 512);

    permute_b2g_kernel<<<nblk, 256>>>(Out, X);

    // ================= Stage 2: 32x32 grid (B=49, N=1024) ===================
    const long long N2 = 1024, NN = N2 * N2;
    launch_dense(X, 128, gp[1], nullptr, nullptr, QKV, 384, 128);
    gemm_mma<<<dim3(8, 16, 196), 256>>>(
        QKV, 384, N2 * 384, 32,
        QKV + 128, 384, N2 * 384, 32,
        S, N2, 4 * NN, NN,
        32, 1024, 0, 1, nullptr, nullptr, gp[0], 32);
    softmax_warp_kernel<<<(196LL * 1024 + 3) / 4, 128>>>(S, 1024, 196LL * 1024);
    gemm_mma<<<dim3(8, 1, 196), 256>>>(
        S, N2, 4 * NN, NN,
        QKV + 256, 384, N2 * 384, 32,
        O, 128, N2 * 128, 32,
        1024, 32, 1, 2, nullptr, nullptr, nullptr, 0);
    launch_dense(O, 128, gp[2], gp[3], X, Y, 128, 128);
    ln_kernel<<<MTOK, 128>>>(Y, gp[4], gp[5], Yn);
    launch_dense(Yn, 128, gp[6], gp[7], nullptr, Z, 512, 128);
    launch_dense(Z, 512, gp[8], gp[9], Yn, Out, 128, 512);

    permute_g2out_kernel<<<nblk, 256>>>(Out, (float*)d_out);
}

// round 4
// speedup vs baseline: 2.9683x; 1.4768x over previous
#include <cuda_runtime.h>
#include <cuda_bf16.h>
#include <math.h>
#include <stdint.h>

// ---------------------------------------------------------------------------
// MaxSA R3: flash-fused attention for both stages; dense GEMMs on mma.sync
// bf16 hi/lo (3-pass). No materialized attention matrix.
// ---------------------------------------------------------------------------

#define CCH   128
#define HWDIM 224
#define MTOK  50176
#define NHEAD 4

__device__ float g_X  [MTOK * CCH];
__device__ float g_QKV[MTOK * 3 * CCH];
__device__ float g_O  [MTOK * CCH];
__device__ float g_Y  [MTOK * CCH];
__device__ float g_Yn [MTOK * CCH];
__device__ float g_Z  [MTOK * 512];
__device__ float g_Out[MTOK * CCH];

// ------------------------- helpers -----------------------------------------
__device__ __forceinline__ float warp_red_sum(float v) {
#pragma unroll
    for (int o = 16; o > 0; o >>= 1) v += __shfl_xor_sync(0xffffffffu, v, o);
    return v;
}
__device__ __forceinline__ uint32_t smem_u32(const void* p) {
    uint32_t a;
    asm("{ .reg .u64 t; cvta.to.shared.u64 t, %1; cvt.u32.u64 %0, t; }" : "=r"(a) : "l"(p));
    return a;
}
__device__ __forceinline__ void mma_bf16(float* c, const uint32_t* a, const uint32_t* b) {
    asm volatile(
        "mma.sync.aligned.m16n8k16.row.col.f32.bf16.bf16.f32 "
        "{%0,%1,%2,%3}, {%4,%5,%6,%7}, {%8,%9}, {%0,%1,%2,%3};"
        : "+f"(c[0]), "+f"(c[1]), "+f"(c[2]), "+f"(c[3])
        : "r"(a[0]), "r"(a[1]), "r"(a[2]), "r"(a[3]), "r"(b[0]), "r"(b[1]));
}
__device__ __forceinline__ void ldm_x4(uint32_t* r, uint32_t addr) {
    asm volatile("ldmatrix.sync.aligned.m8n8.x4.shared.b16 {%0,%1,%2,%3}, [%4];"
                 : "=r"(r[0]), "=r"(r[1]), "=r"(r[2]), "=r"(r[3]) : "r"(addr));
}
__device__ __forceinline__ void ldm_x4_t(uint32_t* r, uint32_t addr) {
    asm volatile("ldmatrix.sync.aligned.m8n8.x4.trans.shared.b16 {%0,%1,%2,%3}, [%4];"
                 : "=r"(r[0]), "=r"(r[1]), "=r"(r[2]), "=r"(r[3]) : "r"(addr));
}
__device__ __forceinline__ void ldm_x2(uint32_t* r, uint32_t addr) {
    asm volatile("ldmatrix.sync.aligned.m8n8.x2.shared.b16 {%0,%1}, [%2];"
                 : "=r"(r[0]), "=r"(r[1]) : "r"(addr));
}
__device__ __forceinline__ uint32_t pack_hi(float x, float y) {
    return (uint32_t)__bfloat16_as_ushort(__float2bfloat16(x)) |
           ((uint32_t)__bfloat16_as_ushort(__float2bfloat16(y)) << 16);
}
__device__ __forceinline__ uint32_t pack_lo(float x, float y) {
    float xh = __bfloat162float(__float2bfloat16(x));
    float yh = __bfloat162float(__float2bfloat16(y));
    return (uint32_t)__bfloat16_as_ushort(__float2bfloat16(x - xh)) |
           ((uint32_t)__bfloat16_as_ushort(__float2bfloat16(y - yh)) << 16);
}

// ---------------------------------------------------------------------------
// Dense GEMM: C[M,N] = A[M,K] @ W[N,K]^T (+bias)(+res). bf16 hi/lo 3-pass.
// Tile 128x64x32, 256 threads. M%128==0, N%64==0, K%32==0.
// ---------------------------------------------------------------------------
#define RS 40

__global__ void __launch_bounds__(256)
gemm_mma(const float* __restrict__ A, const float* __restrict__ W,
         float* __restrict__ C, int K, int N,
         const float* __restrict__ bias, const float* __restrict__ res) {
    __shared__ __align__(16) unsigned short Ah[128 * RS];
    __shared__ __align__(16) unsigned short Al[128 * RS];
    __shared__ __align__(16) unsigned short Bh[64 * RS];
    __shared__ __align__(16) unsigned short Bl[64 * RS];

    int tid = threadIdx.x, wid = tid >> 5, l = tid & 31;
    long long bm = (long long)blockIdx.x * 128;
    int bn = blockIdx.y * 64;
    int wm = (wid >> 1) * 32, wn = (wid & 1) * 32;

    uint32_t uAh = smem_u32(Ah), uAl = smem_u32(Al);
    uint32_t uBh = smem_u32(Bh), uBl = smem_u32(Bl);

    float acc[2][4][4];
#pragma unroll
    for (int i = 0; i < 2; i++)
#pragma unroll
        for (int j = 0; j < 4; j++)
#pragma unroll
            for (int k = 0; k < 4; k++) acc[i][j][k] = 0.f;

    for (int k0 = 0; k0 < K; k0 += 32) {
#pragma unroll
        for (int s = tid; s < 1024; s += 256) {
            int row = s >> 3, kq = s & 7;
            const float* p = A + (bm + row) * K + k0 + kq * 4;
            float4 u = *(const float4*)p;
            *(uint2*)(Ah + row * RS + kq * 4) = make_uint2(pack_hi(u.x, u.y), pack_hi(u.z, u.w));
            *(uint2*)(Al + row * RS + kq * 4) = make_uint2(pack_lo(u.x, u.y), pack_lo(u.z, u.w));
        }
#pragma unroll
        for (int s = tid; s < 512; s += 256) {
            int row = s >> 3, kq = s & 7;
            float4 u = *(const float4*)(W + (size_t)(bn + row) * K + k0 + kq * 4);
            *(uint2*)(Bh + row * RS + kq * 4) = make_uint2(pack_hi(u.x, u.y), pack_hi(u.z, u.w));
            *(uint2*)(Bl + row * RS + kq * 4) = make_uint2(pack_lo(u.x, u.y), pack_lo(u.z, u.w));
        }
        __syncthreads();
#pragma unroll
        for (int s2 = 0; s2 < 2; s2++) {
            int ks = s2 * 16;
            uint32_t ah[2][4], al2[2][4], bh[4][2], bl2[4][2];
            uint32_t aoff = (uint32_t)((wm + (l & 15)) * RS + ks + (l >> 4) * 8) * 2;
            ldm_x4(ah[0], uAh + aoff);
            ldm_x4(al2[0], uAl + aoff);
            ldm_x4(ah[1], uAh + aoff + 16 * RS * 2);
            ldm_x4(al2[1], uAl + aoff + 16 * RS * 2);
            uint32_t boff = (uint32_t)((wn + (l & 7)) * RS + ks + ((l >> 3) & 1) * 8) * 2;
#pragma unroll
            for (int ni = 0; ni < 4; ni++) {
                ldm_x2(bh[ni], uBh + boff + ni * 8 * RS * 2);
                ldm_x2(bl2[ni], uBl + boff + ni * 8 * RS * 2);
            }
#pragma unroll
            for (int mi = 0; mi < 2; mi++)
#pragma unroll
                for (int ni = 0; ni < 4; ni++) {
                    mma_bf16(acc[mi][ni], ah[mi], bh[ni]);
                    mma_bf16(acc[mi][ni], ah[mi], bl2[ni]);
                    mma_bf16(acc[mi][ni], al2[mi], bh[ni]);
                }
        }
        __syncthreads();
    }

    int r0 = wm + (l >> 2);
    int cbase = bn + wn + (l & 3) * 2;
#pragma unroll
    for (int mi = 0; mi < 2; mi++) {
#pragma unroll
        for (int half = 0; half < 2; half++) {
            long long row = bm + r0 + mi * 16 + half * 8;
#pragma unroll
            for (int ni = 0; ni < 4; ni++) {
                int col = cbase + ni * 8;
                float v0 = acc[mi][ni][half * 2 + 0];
                float v1 = acc[mi][ni][half * 2 + 1];
                if (bias) { v0 += bias[col]; v1 += bias[col + 1]; }
                size_t o = (size_t)row * N + col;
                if (res) { v0 += res[o]; v1 += res[o + 1]; }
                *(float2*)(C + o) = make_float2(v0, v1);
            }
        }
    }
}

// ---------------------------------------------------------------------------
// Stage-2 flash attention: B=49, H=4, N=1024, hd=32. One block = (bh, qtile128).
// S/P live in registers; online softmax; bf16 hi/lo 3-pass for both matmuls.
// ---------------------------------------------------------------------------
#define FQH 0
#define FQL 10240
#define FKH 20480
#define FKL 30720
#define FVH 40960
#define FVL 51200
#define FBIAS 61440
#define FSMEM (61440 + 3969 * 4)

__global__ void __launch_bounds__(256)
flash2(const float* __restrict__ QKV, const float* __restrict__ table,
       float* __restrict__ O) {
    extern __shared__ char fsm[];
    uint32_t sb = smem_u32(fsm);
    float* sBias = (float*)(fsm + FBIAS);

    int tid = threadIdx.x, wid = tid >> 5, ln = tid & 31;
    int bh = blockIdx.y, b = bh >> 2, h = bh & 3;
    int bq = blockIdx.x * 128;
    const float* qptr = QKV + (size_t)b * 1024 * 384 + h * 32;

    // rel-pos table for this head -> smem
    for (int i = tid; i < 3969; i += 256) sBias[i] = table[i * 4 + h];

    // Q tile (128x32) -> bf16 hi/lo smem
    for (int s = tid; s < 1024; s += 256) {
        int row = s >> 3, q4 = (s & 7) * 4;
        float4 u = *(const float4*)(qptr + (size_t)(bq + row) * 384 + q4);
        *(uint2*)(fsm + FQH + (row * RS + q4) * 2) = make_uint2(pack_hi(u.x, u.y), pack_hi(u.z, u.w));
        *(uint2*)(fsm + FQL + (row * RS + q4) * 2) = make_uint2(pack_lo(u.x, u.y), pack_lo(u.z, u.w));
    }
    __syncthreads();

    // Q fragments (persistent)
    int rbase = wid * 16;
    uint32_t qh[2][4], ql[2][4];
#pragma unroll
    for (int ks = 0; ks < 2; ks++) {
        uint32_t aoff = (uint32_t)((rbase + (ln & 15)) * RS + ks * 16 + (ln >> 4) * 8) * 2;
        ldm_x4(qh[ks], sb + FQH + aoff);
        ldm_x4(ql[ks], sb + FQL + aoff);
    }

    // accumulators / stats
    float oacc[4][4];
#pragma unroll
    for (int i = 0; i < 4; i++)
#pragma unroll
        for (int j = 0; j < 4; j++) oacc[i][j] = 0.f;
    float m0 = -1e30f, m1 = -1e30f, ls0 = 0.f, ls1 = 0.f;

    int n0 = bq + rbase + (ln >> 2);
    int n1 = n0 + 8;
    int i1a = n0 >> 5, j1a = n0 & 31;
    int i1b = n1 >> 5, j1b = n1 & 31;
    int mcb = 2 * (ln & 3);
    const float SC = 5.656854249492381f;

    for (int kt = 0; kt < 8; kt++) {
        // load K,V tile (128x32 each) -> bf16 hi/lo smem
        const float* kp = qptr + 128 + (size_t)kt * 128 * 384;
        const float* vp = qptr + 256 + (size_t)kt * 128 * 384;
        for (int s = tid; s < 1024; s += 256) {
            int row = s >> 3, q4 = (s & 7) * 4;
            float4 u = *(const float4*)(kp + (size_t)row * 384 + q4);
            *(uint2*)(fsm + FKH + (row * RS + q4) * 2) = make_uint2(pack_hi(u.x, u.y), pack_hi(u.z, u.w));
            *(uint2*)(fsm + FKL + (row * RS + q4) * 2) = make_uint2(pack_lo(u.x, u.y), pack_lo(u.z, u.w));
            float4 v = *(const float4*)(vp + (size_t)row * 384 + q4);
            *(uint2*)(fsm + FVH + (row * RS + q4) * 2) = make_uint2(pack_hi(v.x, v.y), pack_hi(v.z, v.w));
            *(uint2*)(fsm + FVL + (row * RS + q4) * 2) = make_uint2(pack_lo(v.x, v.y), pack_lo(v.z, v.w));
        }
        __syncthreads();

        // ---- S = Q K^T ----
        float sa[16][4];
#pragma unroll
        for (int nf = 0; nf < 16; nf++) {
            sa[nf][0] = sa[nf][1] = sa[nf][2] = sa[nf][3] = 0.f;
            uint32_t bh4[4], bl4[4];
            uint32_t boff = (uint32_t)((nf * 8 + (ln & 7)) * RS + (ln >> 3) * 8) * 2;
            ldm_x4(bh4, sb + FKH + boff);
            ldm_x4(bl4, sb + FKL + boff);
            mma_bf16(sa[nf], qh[0], bh4 + 0);
            mma_bf16(sa[nf], qh[1], bh4 + 2);
            mma_bf16(sa[nf], qh[0], bl4 + 0);
            mma_bf16(sa[nf], qh[1], bl4 + 2);
            mma_bf16(sa[nf], ql[0], bh4 + 0);
            mma_bf16(sa[nf], ql[1], bh4 + 2);
        }

        // ---- bias + scale, row max ----
        float mx0 = -1e30f, mx1 = -1e30f;
#pragma unroll
        for (int nf = 0; nf < 16; nf++) {
            int mc = kt * 128 + nf * 8 + mcb;
            int i2a = mc >> 5, j2a = mc & 31;
            int i2b = (mc + 1) >> 5, j2b = (mc + 1) & 31;
            float s0 = sa[nf][0] * SC + sBias[(i1a - i2a + 31) * 63 + (j1a - j2a + 31)];
            float s1 = sa[nf][1] * SC + sBias[(i1a - i2b + 31) * 63 + (j1a - j2b + 31)];
            float s2 = sa[nf][2] * SC + sBias[(i1b - i2a + 31) * 63 + (j1b - j2a + 31)];
            float s3 = sa[nf][3] * SC + sBias[(i1b - i2b + 31) * 63 + (j1b - j2b + 31)];
            sa[nf][0] = s0; sa[nf][1] = s1; sa[nf][2] = s2; sa[nf][3] = s3;
            mx0 = fmaxf(mx0, fmaxf(s0, s1));
            mx1 = fmaxf(mx1, fmaxf(s2, s3));
        }
        mx0 = fmaxf(mx0, __shfl_xor_sync(0xffffffffu, mx0, 1));
        mx0 = fmaxf(mx0, __shfl_xor_sync(0xffffffffu, mx0, 2));
        mx1 = fmaxf(mx1, __shfl_xor_sync(0xffffffffu, mx1, 1));
        mx1 = fmaxf(mx1, __shfl_xor_sync(0xffffffffu, mx1, 2));
        float mn0 = fmaxf(m0, mx0), mn1 = fmaxf(m1, mx1);
        float f0 = __expf(m0 - mn0), f1 = __expf(m1 - mn1);

        // ---- P = exp(S - m), row sum ----
        float su0 = 0.f, su1 = 0.f;
#pragma unroll
        for (int nf = 0; nf < 16; nf++) {
            float p0 = __expf(sa[nf][0] - mn0);
            float p1 = __expf(sa[nf][1] - mn0);
            float p2 = __expf(sa[nf][2] - mn1);
            float p3 = __expf(sa[nf][3] - mn1);
            sa[nf][0] = p0; sa[nf][1] = p1; sa[nf][2] = p2; sa[nf][3] = p3;
            su0 += p0 + p1; su1 += p2 + p3;
        }
        su0 += __shfl_xor_sync(0xffffffffu, su0, 1);
        su0 += __shfl_xor_sync(0xffffffffu, su0, 2);
        su1 += __shfl_xor_sync(0xffffffffu, su1, 1);
        su1 += __shfl_xor_sync(0xffffffffu, su1, 2);
        ls0 = ls0 * f0 + su0;
        ls1 = ls1 * f1 + su1;
        m0 = mn0; m1 = mn1;

        // rescale O
#pragma unroll
        for (int nd = 0; nd < 4; nd++) {
            oacc[nd][0] *= f0; oacc[nd][1] *= f0;
            oacc[nd][2] *= f1; oacc[nd][3] *= f1;
        }

        // ---- O += P V ----
#pragma unroll
        for (int ks2 = 0; ks2 < 4; ks2++) {
            int k0 = ks2 * 32;
            uint32_t pa0h[4], pa0l[4], pa1h[4], pa1l[4];
            int nfa = 4 * ks2, nfb = nfa + 1, nfc = nfa + 2, nfd = nfa + 3;
            pa0h[0] = pack_hi(sa[nfa][0], sa[nfa][1]);
            pa0h[1] = pack_hi(sa[nfa][2], sa[nfa][3]);
            pa0h[2] = pack_hi(sa[nfb][0], sa[nfb][1]);
            pa0h[3] = pack_hi(sa[nfb][2], sa[nfb][3]);
            pa0l[0] = pack_lo(sa[nfa][0], sa[nfa][1]);
            pa0l[1] = pack_lo(sa[nfa][2], sa[nfa][3]);
            pa0l[2] = pack_lo(sa[nfb][0], sa[nfb][1]);
            pa0l[3] = pack_lo(sa[nfb][2], sa[nfb][3]);
            pa1h[0] = pack_hi(sa[nfc][0], sa[nfc][1]);
            pa1h[1] = pack_hi(sa[nfc][2], sa[nfc][3]);
            pa1h[2] = pack_hi(sa[nfd][0], sa[nfd][1]);
            pa1h[3] = pack_hi(sa[nfd][2], sa[nfd][3]);
            pa1l[0] = pack_lo(sa[nfc][0], sa[nfc][1]);
            pa1l[1] = pack_lo(sa[nfc][2], sa[nfc][3]);
            pa1l[2] = pack_lo(sa[nfd][0], sa[nfd][1]);
            pa1l[3] = pack_lo(sa[nfd][2], sa[nfd][3]);
#pragma unroll
            for (int nd = 0; nd < 4; nd++) {
                uint32_t vh4[4], vl4[4];
                uint32_t voff = (uint32_t)((k0 + (ln >> 3) * 8 + (ln & 7)) * RS + nd * 8) * 2;
                ldm_x4_t(vh4, sb + FVH + voff);
                ldm_x4_t(vl4, sb + FVL + voff);
                mma_bf16(oacc[nd], pa0h, vh4 + 0);
                mma_bf16(oacc[nd], pa1h, vh4 + 2);
                mma_bf16(oacc[nd], pa0h, vl4 + 0);
                mma_bf16(oacc[nd], pa1h, vl4 + 2);
                mma_bf16(oacc[nd], pa0l, vh4 + 0);
                mma_bf16(oacc[nd], pa1l, vh4 + 2);
            }
        }
        __syncthreads();
    }

    // ---- normalize + write ----
    float inv0 = 1.0f / ls0, inv1 = 1.0f / ls1;
    size_t ob = ((size_t)b * 1024) * 128 + h * 32;
#pragma unroll
    for (int nd = 0; nd < 4; nd++) {
        int d = nd * 8 + mcb;
        *(float2*)(O + ob + (size_t)n0 * 128 + d) =
            make_float2(oacc[nd][0] * inv0, oacc[nd][1] * inv0);
        *(float2*)(O + ob + (size_t)n1 * 128 + d) =
            make_float2(oacc[nd][2] * inv1, oacc[nd][3] * inv1);
    }
}

// ---------------------------------------------------------------------------
// Stage-1 fused attention: one block per (window,head), N=49, win=7, fp32 SIMT.
// ---------------------------------------------------------------------------
__global__ void __launch_bounds__(128)
attn_small(const float* __restrict__ QKV, const float* __restrict__ table,
           float* __restrict__ O) {
    __shared__ float sQ[49 * 33];
    __shared__ float sK[49 * 33];
    __shared__ float sV[49 * 33];
    __shared__ float sS[49 * 52];
    __shared__ float sT[169];

    int tid = threadIdx.x;
    int bh = blockIdx.x, b = bh >> 2, h = bh & 3;
    const float* base = QKV + (size_t)b * 49 * 384 + h * 32;

    for (int i = tid; i < 169; i += 128) sT[i] = table[i * 4 + h];
    for (int i = tid; i < 49 * 32; i += 128) {
        int n = i >> 5, d = i & 31;
        sQ[n * 33 + d] = base[(size_t)n * 384 + d];
        sK[n * 33 + d] = base[(size_t)n * 384 + 128 + d];
        sV[n * 33 + d] = base[(size_t)n * 384 + 256 + d];
    }
    __syncthreads();

    const float SC = 5.656854249492381f;
    for (int e = tid; e < 2401; e += 128) {
        int n = e / 49, m = e % 49;
        const float* q = sQ + n * 33;
        const float* k = sK + m * 33;
        float s = 0.f;
#pragma unroll
        for (int d = 0; d < 32; d++) s += q[d] * k[d];
        int i1 = n / 7, j1 = n % 7, i2 = m / 7, j2 = m % 7;
        sS[n * 52 + m] = s * SC + sT[(i1 - i2 + 6) * 13 + (j1 - j2 + 6)];
    }
    __syncthreads();

    if (tid < 49) {
        float* row = sS + tid * 52;
        float mx = -1e30f;
#pragma unroll
        for (int m = 0; m < 49; m++) mx = fmaxf(mx, row[m]);
        float s = 0.f;
#pragma unroll
        for (int m = 0; m < 49; m++) {
            float e = __expf(row[m] - mx);
            row[m] = e;
            s += e;
        }
        float inv = 1.0f / s;
#pragma unroll
        for (int m = 0; m < 49; m++) row[m] *= inv;
    }
    __syncthreads();

    for (int e = tid; e < 49 * 32; e += 128) {
        int n = e >> 5, d = e & 31;
        const float* p = sS + n * 52;
        float s = 0.f;
#pragma unroll
        for (int m = 0; m < 49; m++) s += p[m] * sV[m * 33 + d];
        O[((size_t)b * 49 + n) * 128 + h * 32 + d] = s;
    }
}

// ------------------------- permutations ------------------------------------
__global__ void winpart_b_kernel(const float* __restrict__ x, float* __restrict__ X) {
    int idx = blockIdx.x * 256 + threadIdx.x;
    if (idx >= MTOK * CCH) return;
    int c = idx & 127;
    int t = idx >> 7;
    int tok = t % 49;
    int win = t / 49;
    int hi = tok / 7, wi = tok % 7;
    int ho = win >> 5, wo = win & 31;
    X[idx] = x[c * MTOK + (ho * 7 + hi) * HWDIM + wo * 7 + wi];
}
__global__ void permute_b2g_kernel(const float* __restrict__ A, float* __restrict__ Xg) {
    int idx = blockIdx.x * 256 + threadIdx.x;
    if (idx >= MTOK * CCH) return;
    int cg = idx & 127;
    int t = idx >> 7;
    int tok = t & 1023;
    int win = t >> 10;
    int gho = win / 7, gwo = win % 7;
    int ghi = tok >> 5, gwi = tok & 31;
    int h2 = gho * 32 + ghi, w2 = gwo * 32 + gwi;
    int f = (h2 * HWDIM + w2) * CCH + cg;
    int wo = f & 31; f >>= 5;
    int wi = f % 7;  f /= 7;
    int hi = f % 7;  f /= 7;
    int ho = f & 31; f >>= 5;
    int c = f;
    Xg[idx] = A[((ho * 32 + wo) * 49 + (hi * 7 + wi)) * CCH + c];
}
__global__ void permute_g2out_kernel(const float* __restrict__ A, float* __restrict__ out) {
    int idx = blockIdx.x * 256 + threadIdx.x;
    if (idx >= MTOK * CCH) return;
    int w2 = idx % HWDIM;
    int t = idx / HWDIM;
    int h2 = t % HWDIM;
    int c2 = t / HWDIM;
    int f = (h2 * HWDIM + w2) * CCH + c2;
    int gwo = f % 7;  f /= 7;
    int gwi = f & 31; f >>= 5;
    int ghi = f & 31; f >>= 5;
    int gho = f % 7;  f /= 7;
    int c = f;
    out[idx] = A[((gho * 7 + gwo) * 1024 + ghi * 32 + gwi) * CCH + c];
}

// ------------------------- LayerNorm ---------------------------------------
__global__ void ln_kernel(const float* __restrict__ Y, const float* __restrict__ g,
                          const float* __restrict__ bta, float* __restrict__ out) {
    size_t row = blockIdx.x;
    int tid = threadIdx.x;
    __shared__ float sb[4];
    __shared__ float sb2[4];
    float v = Y[row * CCH + tid];
    float s = warp_red_sum(v);
    if ((tid & 31) == 0) sb[tid >> 5] = s;
    __syncthreads();
    float mu = (sb[0] + sb[1] + sb[2] + sb[3]) * (1.0f / 128.0f);
    float d = v - mu;
    float s2 = warp_red_sum(d * d);
    if ((tid & 31) == 0) sb2[tid >> 5] = s2;
    __syncthreads();
    float var = (sb2[0] + sb2[1] + sb2[2] + sb2[3]) * (1.0f / 128.0f);
    float r = rsqrtf(var + 1e-5f);
    out[row * CCH + tid] = d * r * g[tid] + bta[tid];
}

// ------------------------- host orchestration -------------------------------
static void launch_dense(const float* A, const float* W,
                         const float* bias, const float* res,
                         float* C, int N, int K) {
    gemm_mma<<<dim3(MTOK / 128, N / 64), 256>>>(A, W, C, K, N, bias, res);
}

extern "C" void kernel_launch(void* const* d_in, const int* in_sizes, int n_in,
                              void* d_out, int out_size) {
    const float* x = (const float*)d_in[0];
    const float* bp[10];
    const float* gp[10];
    for (int i = 0; i < 10; i++) bp[i] = (const float*)d_in[1 + i];
    for (int i = 0; i < 10; i++) gp[i] = (const float*)d_in[11 + i];

    cudaFuncSetAttribute(flash2, cudaFuncAttributeMaxDynamicSharedMemorySize, FSMEM);

    float *X, *QKV, *O, *Y, *Yn, *Z, *Out;
    cudaGetSymbolAddress((void**)&X, g_X);
    cudaGetSymbolAddress((void**)&QKV, g_QKV);
    cudaGetSymbolAddress((void**)&O, g_O);
    cudaGetSymbolAddress((void**)&Y, g_Y);
    cudaGetSymbolAddress((void**)&Yn, g_Yn);
    cudaGetSymbolAddress((void**)&Z, g_Z);
    cudaGetSymbolAddress((void**)&Out, g_Out);

    const int nblk = (MTOK * CCH + 255) / 256;

    // ================= Stage 1: 7x7 windows (B=1024, N=49) ==================
    winpart_b_kernel<<<nblk, 256>>>(x, X);
    launch_dense(X, bp[1], nullptr, nullptr, QKV, 384, 128);
    attn_small<<<4096, 128>>>(QKV, bp[0], O);
    launch_dense(O, bp[2], bp[3], X, Y, 128, 128);
    ln_kernel<<<MTOK, 128>>>(Y, bp[4], bp[5], Yn);
    launch_dense(Yn, bp[6], bp[7], nullptr, Z, 512, 128);
    launch_dense(Z, bp[8], bp[9], Yn, Out, 128, 512);

    permute_b2g_kernel<<<nblk, 256>>>(Out, X);

    // ================= Stage 2: 32x32 grid (B=49, N=1024) ===================
    launch_dense(X, gp[1], nullptr, nullptr, QKV, 384, 128);
    flash2<<<dim3(8, 196), 256, FSMEM>>>(QKV, gp[0], O);
    launch_dense(O, gp[2], gp[3], X, Y, 128, 128);
    ln_kernel<<<MTOK, 128>>>(Y, gp[4], gp[5], Yn);
    launch_dense(Yn, gp[6], gp[7], nullptr, Z, 512, 128);
    launch_dense(Z, gp[8], gp[9], Yn, Out, 128, 512);

    permute_g2out_kernel<<<nblk, 256>>>(Out, (float*)d_out);
}

// round 5
// speedup vs baseline: 3.5701x; 1.2027x over previous
#include <cuda_runtime.h>
#include <cuda_bf16.h>
#include <stdint.h>

// ---------------------------------------------------------------------------
// MaxSA R4: bf16 hi/lo planes precomputed for every GEMM operand; dense GEMMs
// are pure-HMMA 128x128x32 double-buffered cp.async kernels. Flash attention
// consumes bf16 planes directly.
// ---------------------------------------------------------------------------

#define CCH   128
#define HWDIM 224
#define MTOK  50176

__device__ __align__(16) float g_X  [MTOK * CCH];
__device__ __align__(16) float g_Y  [MTOK * CCH];
__device__ __align__(16) float g_Yn [MTOK * CCH];
__device__ __align__(16) float g_Out[MTOK * CCH];
__device__ __align__(16) __nv_bfloat16 g_Xbf [2u * MTOK * CCH];
__device__ __align__(16) __nv_bfloat16 g_QKVbf[2u * MTOK * 384];
__device__ __align__(16) __nv_bfloat16 g_Obf [2u * MTOK * CCH];
__device__ __align__(16) __nv_bfloat16 g_Ynbf[2u * MTOK * CCH];
__device__ __align__(16) __nv_bfloat16 g_Zbf [2u * MTOK * 512];
__device__ __align__(16) __nv_bfloat16 g_Wbf [786432];

// ------------------------- helpers -----------------------------------------
__device__ __forceinline__ float warp_red_sum(float v) {
#pragma unroll
    for (int o = 16; o > 0; o >>= 1) v += __shfl_xor_sync(0xffffffffu, v, o);
    return v;
}
__device__ __forceinline__ uint32_t smem_u32(const void* p) {
    uint32_t a;
    asm("{ .reg .u64 t; cvta.to.shared.u64 t, %1; cvt.u32.u64 %0, t; }" : "=r"(a) : "l"(p));
    return a;
}
__device__ __forceinline__ void mma_bf16(float* c, const uint32_t* a, const uint32_t* b) {
    asm volatile(
        "mma.sync.aligned.m16n8k16.row.col.f32.bf16.bf16.f32 "
        "{%0,%1,%2,%3}, {%4,%5,%6,%7}, {%8,%9}, {%0,%1,%2,%3};"
        : "+f"(c[0]), "+f"(c[1]), "+f"(c[2]), "+f"(c[3])
        : "r"(a[0]), "r"(a[1]), "r"(a[2]), "r"(a[3]), "r"(b[0]), "r"(b[1]));
}
__device__ __forceinline__ void ldm_x4(uint32_t* r, uint32_t addr) {
    asm volatile("ldmatrix.sync.aligned.m8n8.x4.shared.b16 {%0,%1,%2,%3}, [%4];"
                 : "=r"(r[0]), "=r"(r[1]), "=r"(r[2]), "=r"(r[3]) : "r"(addr));
}
__device__ __forceinline__ void ldm_x4_t(uint32_t* r, uint32_t addr) {
    asm volatile("ldmatrix.sync.aligned.m8n8.x4.trans.shared.b16 {%0,%1,%2,%3}, [%4];"
                 : "=r"(r[0]), "=r"(r[1]), "=r"(r[2]), "=r"(r[3]) : "r"(addr));
}
__device__ __forceinline__ uint32_t pack_hi(float x, float y) {
    return (uint32_t)__bfloat16_as_ushort(__float2bfloat16(x)) |
           ((uint32_t)__bfloat16_as_ushort(__float2bfloat16(y)) << 16);
}
__device__ __forceinline__ uint32_t pack_lo(float x, float y) {
    float xh = __bfloat162float(__float2bfloat16(x));
    float yh = __bfloat162float(__float2bfloat16(y));
    return (uint32_t)__bfloat16_as_ushort(__float2bfloat16(x - xh)) |
           ((uint32_t)__bfloat16_as_ushort(__float2bfloat16(y - yh)) << 16);
}
__device__ __forceinline__ void split_bf(float v, __nv_bfloat16& h, __nv_bfloat16& l) {
    h = __float2bfloat16(v);
    l = __float2bfloat16(v - __bfloat162float(h));
}
__device__ __forceinline__ void cpa16(uint32_t d, const void* s) {
    asm volatile("cp.async.ca.shared.global [%0], [%1], 16;"
                 :: "r"(d), "l"(__cvta_generic_to_global(s)) : "memory");
}
#define CPA_COMMIT asm volatile("cp.async.commit_group;" ::: "memory")
#define CPA_WAIT(n) asm volatile("cp.async.wait_group %0;" :: "n"(n) : "memory")

// ---------------------------------------------------------------------------
// Dense GEMM (bf16-plane inputs): C[M,N] = A @ W^T. A planes: [M,K] hi, +AMK lo.
// Wt planes: [K,N] hi, +WNK lo. Tile 128x128x32, double-buffered cp.async.
// Output: Cbf!=null -> bf16 planes (+bias); else fp32 C (+bias)(+res).
// ---------------------------------------------------------------------------
#define RSA 40
#define RSB 136
#define ASZ (128 * RSA * 2)
#define BSZ (32 * RSB * 2)
#define STG (2 * ASZ + 2 * BSZ)
#define GSMEM (2 * STG)

__global__ void __launch_bounds__(256, 2)
gemm_bf(const __nv_bfloat16* __restrict__ A, long long AMK,
        const __nv_bfloat16* __restrict__ Wt, long long WNK,
        int K, int N,
        const float* __restrict__ bias, const float* __restrict__ res,
        float* __restrict__ C, __nv_bfloat16* __restrict__ Cbf, long long CMK) {
    extern __shared__ char sm[];
    uint32_t sb = smem_u32(sm);
    int tid = threadIdx.x, wid = tid >> 5, l = tid & 31;
    long long bm = (long long)blockIdx.x * 128;
    int bn = blockIdx.y * 128;
    int wm = (wid & 3) * 32, wn = (wid >> 2) * 64;
    int nc = K >> 5;

    auto load_tile = [&](int st, int cc) {
        int k0 = cc << 5;
        uint32_t base = sb + st * STG;
#pragma unroll
        for (int i = tid; i < 1024; i += 256) {
            int pl = i >> 9;
            int r = (i >> 2) & 127;
            int c4 = (i & 3) * 8;
            cpa16(base + pl * ASZ + (r * RSA + c4) * 2,
                  A + pl * AMK + (bm + r) * K + k0 + c4);
        }
#pragma unroll
        for (int i = tid; i < 1024; i += 256) {
            int pl = i >> 9;
            int r = (i >> 4) & 31;
            int c8 = (i & 15) * 8;
            cpa16(base + 2 * ASZ + pl * BSZ + (r * RSB + c8) * 2,
                  Wt + pl * WNK + (size_t)(k0 + r) * N + bn + c8);
        }
    };

    float acc[2][8][4];
#pragma unroll
    for (int a = 0; a < 2; a++)
#pragma unroll
        for (int b = 0; b < 8; b++)
#pragma unroll
            for (int c = 0; c < 4; c++) acc[a][b][c] = 0.f;

    load_tile(0, 0);
    CPA_COMMIT;
    for (int c = 0; c < nc; c++) {
        if (c + 1 < nc) {
            load_tile((c + 1) & 1, c + 1);
            CPA_COMMIT;
            CPA_WAIT(1);
        } else {
            CPA_WAIT(0);
        }
        __syncthreads();
        uint32_t base = sb + (c & 1) * STG;

        uint32_t ah[2][2][4], al[2][2][4];
#pragma unroll
        for (int ks = 0; ks < 2; ks++)
#pragma unroll
            for (int mi = 0; mi < 2; mi++) {
                uint32_t ao = base + ((wm + mi * 16 + (l & 15)) * RSA + ks * 16 + (l >> 4) * 8) * 2;
                ldm_x4(ah[ks][mi], ao);
                ldm_x4(al[ks][mi], ao + ASZ);
            }
#pragma unroll
        for (int nf = 0; nf < 8; nf++) {
            uint32_t bo = base + 2 * ASZ +
                          ((((l >> 3) * 8) + (l & 7)) * RSB + wn + nf * 8) * 2;
            uint32_t bh[4], bl[4];
            ldm_x4_t(bh, bo);
            ldm_x4_t(bl, bo + BSZ);
#pragma unroll
            for (int ks = 0; ks < 2; ks++)
#pragma unroll
                for (int mi = 0; mi < 2; mi++) {
                    mma_bf16(acc[mi][nf], ah[ks][mi], bh + ks * 2);
                    mma_bf16(acc[mi][nf], ah[ks][mi], bl + ks * 2);
                    mma_bf16(acc[mi][nf], al[ks][mi], bh + ks * 2);
                }
        }
        __syncthreads();
    }

    int r0 = wm + (l >> 2);
    int cb = bn + wn + (l & 3) * 2;
#pragma unroll
    for (int mi = 0; mi < 2; mi++) {
#pragma unroll
        for (int half = 0; half < 2; half++) {
            long long row = bm + r0 + mi * 16 + half * 8;
#pragma unroll
            for (int nf = 0; nf < 8; nf++) {
                int col = cb + nf * 8;
                float v0 = acc[mi][nf][half * 2 + 0];
                float v1 = acc[mi][nf][half * 2 + 1];
                if (bias) { v0 += bias[col]; v1 += bias[col + 1]; }
                size_t o = (size_t)row * N + col;
                if (Cbf) {
                    __nv_bfloat16 h0, l0, h1, l1;
                    split_bf(v0, h0, l0);
                    split_bf(v1, h1, l1);
                    __nv_bfloat162 hh; hh.x = h0; hh.y = h1;
                    __nv_bfloat162 ll; ll.x = l0; ll.y = l1;
                    *(__nv_bfloat162*)(Cbf + o) = hh;
                    *(__nv_bfloat162*)(Cbf + CMK + o) = ll;
                } else {
                    if (res) { v0 += res[o]; v1 += res[o + 1]; }
                    *(float2*)(C + o) = make_float2(v0, v1);
                }
            }
        }
    }
}

// ---------------------------------------------------------------------------
// Stage-2 flash attention (bf16-plane QKV in, bf16-plane O out).
// ---------------------------------------------------------------------------
#define FQH 0
#define FKH 20480
#define FVH 40960
#define FBIAS 61440
#define FSMEM (61440 + 3969 * 4)

__global__ void __launch_bounds__(256)
flash2(const __nv_bfloat16* __restrict__ QKVbf, const float* __restrict__ table,
       __nv_bfloat16* __restrict__ Obf) {
    extern __shared__ char fsm[];
    uint32_t sb = smem_u32(fsm);
    float* sBias = (float*)(fsm + FBIAS);

    int tid = threadIdx.x, wid = tid >> 5, ln = tid & 31;
    int bh = blockIdx.y, b = bh >> 2, h = bh & 3;
    int bq = blockIdx.x * 128;
    const long long QMK = (long long)MTOK * 384;
    const long long OMK = (long long)MTOK * 128;
    long long tok0 = (long long)b * 1024;

    for (int i = tid; i < 3969; i += 256) sBias[i] = table[i * 4 + h];

    // Q planes -> smem
#pragma unroll
    for (int i = tid; i < 1024; i += 256) {
        int pl = i >> 9, r = (i >> 2) & 127, c4 = (i & 3) * 8;
        cpa16(sb + FQH + pl * 10240 + (r * RSA + c4) * 2,
              QKVbf + pl * QMK + (tok0 + bq + r) * 384 + h * 32 + c4);
    }
    CPA_COMMIT;
    CPA_WAIT(0);
    __syncthreads();

    int rbase = wid * 16;
    uint32_t qh[2][4], ql[2][4];
#pragma unroll
    for (int ks = 0; ks < 2; ks++) {
        uint32_t ao = sb + FQH + ((rbase + (ln & 15)) * RSA + ks * 16 + (ln >> 4) * 8) * 2;
        ldm_x4(qh[ks], ao);
        ldm_x4(ql[ks], ao + 10240);
    }

    float oacc[4][4];
#pragma unroll
    for (int i = 0; i < 4; i++)
#pragma unroll
        for (int j = 0; j < 4; j++) oacc[i][j] = 0.f;
    float m0 = -1e30f, m1 = -1e30f, ls0 = 0.f, ls1 = 0.f;

    int n0 = bq + rbase + (ln >> 2);
    int n1 = n0 + 8;
    int i1a = n0 >> 5, j1a = n0 & 31;
    int i1b = n1 >> 5, j1b = n1 & 31;
    int mcb = 2 * (ln & 3);
    const float SC = 5.656854249492381f;

    for (int kt = 0; kt < 8; kt++) {
        // K,V planes -> smem
#pragma unroll
        for (int i = tid; i < 2048; i += 256) {
            int tensor = i >> 10;
            int pl = (i >> 9) & 1;
            int r = (i >> 2) & 127, c4 = (i & 3) * 8;
            cpa16(sb + FKH + tensor * 20480 + pl * 10240 + (r * RSA + c4) * 2,
                  QKVbf + pl * QMK + (tok0 + kt * 128 + r) * 384 + 128 + tensor * 128 + h * 32 + c4);
        }
        CPA_COMMIT;
        CPA_WAIT(0);
        __syncthreads();

        // ---- S = Q K^T ----
        float sa[16][4];
#pragma unroll
        for (int nf = 0; nf < 16; nf++) {
            sa[nf][0] = sa[nf][1] = sa[nf][2] = sa[nf][3] = 0.f;
            uint32_t bh4[4], bl4[4];
            uint32_t bo = sb + FKH + ((nf * 8 + (ln & 7)) * RSA + (ln >> 3) * 8) * 2;
            ldm_x4(bh4, bo);
            ldm_x4(bl4, bo + 10240);
            mma_bf16(sa[nf], qh[0], bh4 + 0);
            mma_bf16(sa[nf], qh[1], bh4 + 2);
            mma_bf16(sa[nf], qh[0], bl4 + 0);
            mma_bf16(sa[nf], qh[1], bl4 + 2);
            mma_bf16(sa[nf], ql[0], bh4 + 0);
            mma_bf16(sa[nf], ql[1], bh4 + 2);
        }

        // ---- bias + scale, row max ----
        float mx0 = -1e30f, mx1 = -1e30f;
#pragma unroll
        for (int nf = 0; nf < 16; nf++) {
            int mc = kt * 128 + nf * 8 + mcb;
            int i2a = mc >> 5, j2a = mc & 31;
            int i2b = (mc + 1) >> 5, j2b = (mc + 1) & 31;
            float s0 = sa[nf][0] * SC + sBias[(i1a - i2a + 31) * 63 + (j1a - j2a + 31)];
            float s1 = sa[nf][1] * SC + sBias[(i1a - i2b + 31) * 63 + (j1a - j2b + 31)];
            float s2 = sa[nf][2] * SC + sBias[(i1b - i2a + 31) * 63 + (j1b - j2a + 31)];
            float s3 = sa[nf][3] * SC + sBias[(i1b - i2b + 31) * 63 + (j1b - j2b + 31)];
            sa[nf][0] = s0; sa[nf][1] = s1; sa[nf][2] = s2; sa[nf][3] = s3;
            mx0 = fmaxf(mx0, fmaxf(s0, s1));
            mx1 = fmaxf(mx1, fmaxf(s2, s3));
        }
        mx0 = fmaxf(mx0, __shfl_xor_sync(0xffffffffu, mx0, 1));
        mx0 = fmaxf(mx0, __shfl_xor_sync(0xffffffffu, mx0, 2));
        mx1 = fmaxf(mx1, __shfl_xor_sync(0xffffffffu, mx1, 1));
        mx1 = fmaxf(mx1, __shfl_xor_sync(0xffffffffu, mx1, 2));
        float mn0 = fmaxf(m0, mx0), mn1 = fmaxf(m1, mx1);
        float f0 = __expf(m0 - mn0), f1 = __expf(m1 - mn1);

        float su0 = 0.f, su1 = 0.f;
#pragma unroll
        for (int nf = 0; nf < 16; nf++) {
            float p0 = __expf(sa[nf][0] - mn0);
            float p1 = __expf(sa[nf][1] - mn0);
            float p2 = __expf(sa[nf][2] - mn1);
            float p3 = __expf(sa[nf][3] - mn1);
            sa[nf][0] = p0; sa[nf][1] = p1; sa[nf][2] = p2; sa[nf][3] = p3;
            su0 += p0 + p1; su1 += p2 + p3;
        }
        su0 += __shfl_xor_sync(0xffffffffu, su0, 1);
        su0 += __shfl_xor_sync(0xffffffffu, su0, 2);
        su1 += __shfl_xor_sync(0xffffffffu, su1, 1);
        su1 += __shfl_xor_sync(0xffffffffu, su1, 2);
        ls0 = ls0 * f0 + su0;
        ls1 = ls1 * f1 + su1;
        m0 = mn0; m1 = mn1;

#pragma unroll
        for (int nd = 0; nd < 4; nd++) {
            oacc[nd][0] *= f0; oacc[nd][1] *= f0;
            oacc[nd][2] *= f1; oacc[nd][3] *= f1;
        }

        // ---- O += P V ----
#pragma unroll
        for (int ks2 = 0; ks2 < 4; ks2++) {
            int k0 = ks2 * 32;
            uint32_t pa0h[4], pa0l[4], pa1h[4], pa1l[4];
            int nfa = 4 * ks2, nfb = nfa + 1, nfc = nfa + 2, nfd = nfa + 3;
            pa0h[0] = pack_hi(sa[nfa][0], sa[nfa][1]);
            pa0h[1] = pack_hi(sa[nfa][2], sa[nfa][3]);
            pa0h[2] = pack_hi(sa[nfb][0], sa[nfb][1]);
            pa0h[3] = pack_hi(sa[nfb][2], sa[nfb][3]);
            pa0l[0] = pack_lo(sa[nfa][0], sa[nfa][1]);
            pa0l[1] = pack_lo(sa[nfa][2], sa[nfa][3]);
            pa0l[2] = pack_lo(sa[nfb][0], sa[nfb][1]);
            pa0l[3] = pack_lo(sa[nfb][2], sa[nfb][3]);
            pa1h[0] = pack_hi(sa[nfc][0], sa[nfc][1]);
            pa1h[1] = pack_hi(sa[nfc][2], sa[nfc][3]);
            pa1h[2] = pack_hi(sa[nfd][0], sa[nfd][1]);
            pa1h[3] = pack_hi(sa[nfd][2], sa[nfd][3]);
            pa1l[0] = pack_lo(sa[nfc][0], sa[nfc][1]);
            pa1l[1] = pack_lo(sa[nfc][2], sa[nfc][3]);
            pa1l[2] = pack_lo(sa[nfd][0], sa[nfd][1]);
            pa1l[3] = pack_lo(sa[nfd][2], sa[nfd][3]);
#pragma unroll
            for (int nd = 0; nd < 4; nd++) {
                uint32_t vh4[4], vl4[4];
                uint32_t vo = sb + FVH + ((k0 + (ln >> 3) * 8 + (ln & 7)) * RSA + nd * 8) * 2;
                ldm_x4_t(vh4, vo);
                ldm_x4_t(vl4, vo + 10240);
                mma_bf16(oacc[nd], pa0h, vh4 + 0);
                mma_bf16(oacc[nd], pa1h, vh4 + 2);
                mma_bf16(oacc[nd], pa0h, vl4 + 0);
                mma_bf16(oacc[nd], pa1h, vl4 + 2);
                mma_bf16(oacc[nd], pa0l, vh4 + 0);
                mma_bf16(oacc[nd], pa1l, vh4 + 2);
            }
        }
        __syncthreads();
    }

    float inv0 = 1.0f / ls0, inv1 = 1.0f / ls1;
    size_t o0 = (size_t)(tok0 + n0) * 128 + h * 32;
    size_t o1 = (size_t)(tok0 + n1) * 128 + h * 32;
#pragma unroll
    for (int nd = 0; nd < 4; nd++) {
        int d = nd * 8 + mcb;
        float a0 = oacc[nd][0] * inv0, a1 = oacc[nd][1] * inv0;
        float b0 = oacc[nd][2] * inv1, b1 = oacc[nd][3] * inv1;
        __nv_bfloat16 h0, l0, h1, l1;
        split_bf(a0, h0, l0); split_bf(a1, h1, l1);
        __nv_bfloat162 hh; hh.x = h0; hh.y = h1;
        __nv_bfloat162 ll; ll.x = l0; ll.y = l1;
        *(__nv_bfloat162*)(Obf + o0 + d) = hh;
        *(__nv_bfloat162*)(Obf + OMK + o0 + d) = ll;
        split_bf(b0, h0, l0); split_bf(b1, h1, l1);
        hh.x = h0; hh.y = h1; ll.x = l0; ll.y = l1;
        *(__nv_bfloat162*)(Obf + o1 + d) = hh;
        *(__nv_bfloat162*)(Obf + OMK + o1 + d) = ll;
    }
}

// ---------------------------------------------------------------------------
// Stage-1 fused attention: one block per (window,head), N=49, fp32 SIMT.
// Reads bf16 QKV planes (hi+lo reconstruct), writes bf16 O planes.
// ---------------------------------------------------------------------------
__global__ void __launch_bounds__(128)
attn_small(const __nv_bfloat16* __restrict__ QKVbf, const float* __restrict__ table,
           __nv_bfloat16* __restrict__ Obf) {
    __shared__ float sQ[49 * 33];
    __shared__ float sK[49 * 33];
    __shared__ float sV[49 * 33];
    __shared__ float sS[49 * 52];
    __shared__ float sT[169];

    const long long QMK = (long long)MTOK * 384;
    const long long OMK = (long long)MTOK * 128;
    int tid = threadIdx.x;
    int bh = blockIdx.x, b = bh >> 2, h = bh & 3;
    const __nv_bfloat16* hi = QKVbf + (long long)b * 49 * 384 + h * 32;
    const __nv_bfloat16* lo = hi + QMK;

    for (int i = tid; i < 169; i += 128) sT[i] = table[i * 4 + h];
    for (int i = tid; i < 49 * 32; i += 128) {
        int n = i >> 5, d = i & 31;
        long long off = (long long)n * 384 + d;
        sQ[n * 33 + d] = __bfloat162float(hi[off]) + __bfloat162float(lo[off]);
        sK[n * 33 + d] = __bfloat162float(hi[off + 128]) + __bfloat162float(lo[off + 128]);
        sV[n * 33 + d] = __bfloat162float(hi[off + 256]) + __bfloat162float(lo[off + 256]);
    }
    __syncthreads();

    const float SC = 5.656854249492381f;
    for (int e = tid; e < 2401; e += 128) {
        int n = e / 49, m = e % 49;
        const float* q = sQ + n * 33;
        const float* k = sK + m * 33;
        float s = 0.f;
#pragma unroll
        for (int d = 0; d < 32; d++) s += q[d] * k[d];
        int i1 = n / 7, j1 = n % 7, i2 = m / 7, j2 = m % 7;
        sS[n * 52 + m] = s * SC + sT[(i1 - i2 + 6) * 13 + (j1 - j2 + 6)];
    }
    __syncthreads();

    if (tid < 49) {
        float* row = sS + tid * 52;
        float mx = -1e30f;
#pragma unroll
        for (int m = 0; m < 49; m++) mx = fmaxf(mx, row[m]);
        float s = 0.f;
#pragma unroll
        for (int m = 0; m < 49; m++) {
            float e = __expf(row[m] - mx);
            row[m] = e;
            s += e;
        }
        float inv = 1.0f / s;
#pragma unroll
        for (int m = 0; m < 49; m++) row[m] *= inv;
    }
    __syncthreads();

    for (int e = tid; e < 49 * 32; e += 128) {
        int n = e >> 5, d = e & 31;
        const float* p = sS + n * 52;
        float s = 0.f;
#pragma unroll
        for (int m = 0; m < 49; m++) s += p[m] * sV[m * 33 + d];
        long long o = ((long long)b * 49 + n) * 128 + h * 32 + d;
        __nv_bfloat16 hh, ll;
        split_bf(s, hh, ll);
        Obf[o] = hh;
        Obf[OMK + o] = ll;
    }
}

// ------------------------- permutations ------------------------------------
__global__ void winpart_b_kernel(const float* __restrict__ x, float* __restrict__ X,
                                 __nv_bfloat16* __restrict__ Xbf) {
    const long long XMK = (long long)MTOK * 128;
    int idx = blockIdx.x * 256 + threadIdx.x;
    if (idx >= MTOK * CCH) return;
    int c = idx & 127;
    int t = idx >> 7;
    int tok = t % 49;
    int win = t / 49;
    int hi2 = tok / 7, wi = tok % 7;
    int ho = win >> 5, wo = win & 31;
    float v = x[c * MTOK + (ho * 7 + hi2) * HWDIM + wo * 7 + wi];
    X[idx] = v;
    __nv_bfloat16 h, l;
    split_bf(v, h, l);
    Xbf[idx] = h;
    Xbf[XMK + idx] = l;
}
__global__ void permute_b2g_kernel(const float* __restrict__ A, float* __restrict__ Xg,
                                   __nv_bfloat16* __restrict__ Xbf) {
    const long long XMK = (long long)MTOK * 128;
    int idx = blockIdx.x * 256 + threadIdx.x;
    if (idx >= MTOK * CCH) return;
    int cg = idx & 127;
    int t = idx >> 7;
    int tok = t & 1023;
    int win = t >> 10;
    int gho = win / 7, gwo = win % 7;
    int ghi = tok >> 5, gwi = tok & 31;
    int h2 = gho * 32 + ghi, w2 = gwo * 32 + gwi;
    int f = (h2 * HWDIM + w2) * CCH + cg;
    int wo = f & 31; f >>= 5;
    int wi = f % 7;  f /= 7;
    int hi2 = f % 7; f /= 7;
    int ho = f & 31; f >>= 5;
    int c = f;
    float v = A[((ho * 32 + wo) * 49 + (hi2 * 7 + wi)) * CCH + c];
    Xg[idx] = v;
    __nv_bfloat16 h, l;
    split_bf(v, h, l);
    Xbf[idx] = h;
    Xbf[XMK + idx] = l;
}
__global__ void permute_g2out_kernel(const float* __restrict__ A, float* __restrict__ out) {
    int idx = blockIdx.x * 256 + threadIdx.x;
    if (idx >= MTOK * CCH) return;
    int w2 = idx % HWDIM;
    int t = idx / HWDIM;
    int h2 = t % HWDIM;
    int c2 = t / HWDIM;
    int f = (h2 * HWDIM + w2) * CCH + c2;
    int gwo = f % 7;  f /= 7;
    int gwi = f & 31; f >>= 5;
    int ghi = f & 31; f >>= 5;
    int gho = f % 7;  f /= 7;
    int c = f;
    out[idx] = A[((gho * 7 + gwo) * 1024 + ghi * 32 + gwi) * CCH + c];
}

// ------------------------- LayerNorm (fp32 + bf16 planes) -------------------
__global__ void ln_kernel(const float* __restrict__ Y, const float* __restrict__ g,
                          const float* __restrict__ bta, float* __restrict__ out,
                          __nv_bfloat16* __restrict__ outbf) {
    const long long XMK = (long long)MTOK * 128;
    size_t row = blockIdx.x;
    int tid = threadIdx.x;
    __shared__ float sb[4];
    __shared__ float sb2[4];
    float v = Y[row * CCH + tid];
    float s = warp_red_sum(v);
    if ((tid & 31) == 0) sb[tid >> 5] = s;
    __syncthreads();
    float mu = (sb[0] + sb[1] + sb[2] + sb[3]) * (1.0f / 128.0f);
    float d = v - mu;
    float s2 = warp_red_sum(d * d);
    if ((tid & 31) == 0) sb2[tid >> 5] = s2;
    __syncthreads();
    float var = (sb2[0] + sb2[1] + sb2[2] + sb2[3]) * (1.0f / 128.0f);
    float r = rsqrtf(var + 1e-5f);
    float val = d * r * g[tid] + bta[tid];
    out[row * CCH + tid] = val;
    __nv_bfloat16 h, l;
    split_bf(val, h, l);
    outbf[row * CCH + tid] = h;
    outbf[XMK + row * CCH + tid] = l;
}

// ------------------------- weight pre-split (transposed) --------------------
__global__ void convw(const float* __restrict__ W, __nv_bfloat16* __restrict__ dst,
                      int N, int K) {
    int idx = blockIdx.x * 256 + threadIdx.x;
    if (idx >= N * K) return;
    int n = idx / K, k = idx % K;
    float v = W[idx];
    __nv_bfloat16 h, l;
    split_bf(v, h, l);
    dst[(size_t)k * N + n] = h;
    dst[(size_t)N * K + (size_t)k * N + n] = l;
}

// ------------------------- host orchestration -------------------------------
extern "C" void kernel_launch(void* const* d_in, const int* in_sizes, int n_in,
                              void* d_out, int out_size) {
    const float* x = (const float*)d_in[0];
    const float* bp[10];
    const float* gp[10];
    for (int i = 0; i < 10; i++) bp[i] = (const float*)d_in[1 + i];
    for (int i = 0; i < 10; i++) gp[i] = (const float*)d_in[11 + i];

    cudaFuncSetAttribute(gemm_bf, cudaFuncAttributeMaxDynamicSharedMemorySize, GSMEM);
    cudaFuncSetAttribute(flash2, cudaFuncAttributeMaxDynamicSharedMemorySize, FSMEM);

    float *X, *Y, *Yn, *Out;
    __nv_bfloat16 *Xbf, *QKVbf, *Obf, *Ynbf, *Zbf, *Wbf;
    cudaGetSymbolAddress((void**)&X, g_X);
    cudaGetSymbolAddress((void**)&Y, g_Y);
    cudaGetSymbolAddress((void**)&Yn, g_Yn);
    cudaGetSymbolAddress((void**)&Out, g_Out);
    cudaGetSymbolAddress((void**)&Xbf, g_Xbf);
    cudaGetSymbolAddress((void**)&QKVbf, g_QKVbf);
    cudaGetSymbolAddress((void**)&Obf, g_Obf);
    cudaGetSymbolAddress((void**)&Ynbf, g_Ynbf);
    cudaGetSymbolAddress((void**)&Zbf, g_Zbf);
    cudaGetSymbolAddress((void**)&Wbf, g_Wbf);

    const long long XMK = (long long)MTOK * 128;
    const long long QMK = (long long)MTOK * 384;
    const long long ZMK = (long long)MTOK * 512;
    const int nblk = (MTOK * CCH + 255) / 256;

    // ---- weight pre-split (hi/lo planes, [K,N] layout) ----
    // offsets in elements: qkv 2*49152, proj 2*16384, fc1 2*65536, fc2 2*65536
    convw<<<192, 256>>>(bp[1], Wbf + 0, 384, 128);
    convw<<<64, 256>>>(bp[2], Wbf + 98304, 128, 128);
    convw<<<256, 256>>>(bp[6], Wbf + 131072, 512, 128);
    convw<<<256, 256>>>(bp[8], Wbf + 262144, 128, 512);
    convw<<<192, 256>>>(gp[1], Wbf + 393216, 384, 128);
    convw<<<64, 256>>>(gp[2], Wbf + 491520, 128, 128);
    convw<<<256, 256>>>(gp[6], Wbf + 524288, 512, 128);
    convw<<<256, 256>>>(gp[8], Wbf + 655360, 128, 512);

    // ================= Stage 1: 7x7 windows ==================
    winpart_b_kernel<<<nblk, 256>>>(x, X, Xbf);
    gemm_bf<<<dim3(392, 3), 256, GSMEM>>>(Xbf, XMK, Wbf + 0, 49152, 128, 384,
                                          nullptr, nullptr, nullptr, QKVbf, QMK);
    attn_small<<<4096, 128>>>(QKVbf, bp[0], Obf);
    gemm_bf<<<dim3(392, 1), 256, GSMEM>>>(Obf, XMK, Wbf + 98304, 16384, 128, 128,
                                          bp[3], X, Y, nullptr, 0);
    ln_kernel<<<MTOK, 128>>>(Y, bp[4], bp[5], Yn, Ynbf);
    gemm_bf<<<dim3(392, 4), 256, GSMEM>>>(Ynbf, XMK, Wbf + 131072, 65536, 128, 512,
                                          bp[7], nullptr, nullptr, Zbf, ZMK);
    gemm_bf<<<dim3(392, 1), 256, GSMEM>>>(Zbf, ZMK, Wbf + 262144, 65536, 512, 128,
                                          bp[9], Yn, Out, nullptr, 0);

    permute_b2g_kernel<<<nblk, 256>>>(Out, X, Xbf);

    // ================= Stage 2: 32x32 grid ===================
    gemm_bf<<<dim3(392, 3), 256, GSMEM>>>(Xbf, XMK, Wbf + 393216, 49152, 128, 384,
                                          nullptr, nullptr, nullptr, QKVbf, QMK);
    flash2<<<dim3(8, 196), 256, FSMEM>>>(QKVbf, gp[0], Obf);
    gemm_bf<<<dim3(392, 1), 256, GSMEM>>>(Obf, XMK, Wbf + 491520, 16384, 128, 128,
                                          gp[3], X, Y, nullptr, 0);
    ln_kernel<<<MTOK, 128>>>(Y, gp[4], gp[5], Yn, Ynbf);
    gemm_bf<<<dim3(392, 4), 256, GSMEM>>>(Ynbf, XMK, Wbf + 524288, 65536, 128, 512,
                                          gp[7], nullptr, nullptr, Zbf, ZMK);
    gemm_bf<<<dim3(392, 1), 256, GSMEM>>>(Zbf, ZMK, Wbf + 655360, 65536, 512, 128,
                                          gp[9], Yn, Out, nullptr, 0);

    permute_g2out_kernel<<<nblk, 256>>>(Out, (float*)d_out);
}

// round 6
// speedup vs baseline: 4.0450x; 1.1330x over previous
#include <cuda_runtime.h>
#include <cuda_bf16.h>
#include <stdint.h>

// ---------------------------------------------------------------------------
// MaxSA R5: LN fused into proj-GEMM epilogue; tensor-core stage1 attention;
// single weight-split kernel; coalesced window partition.
// ---------------------------------------------------------------------------

#define CCH   128
#define HWDIM 224
#define MTOK  50176

__device__ __align__(16) float g_X  [MTOK * CCH];
__device__ __align__(16) float g_Yn [MTOK * CCH];
__device__ __align__(16) float g_Out[MTOK * CCH];
__device__ __align__(16) __nv_bfloat16 g_Xbf [2u * MTOK * CCH];
__device__ __align__(16) __nv_bfloat16 g_QKVbf[2u * MTOK * 384];
__device__ __align__(16) __nv_bfloat16 g_Obf [2u * MTOK * CCH];
__device__ __align__(16) __nv_bfloat16 g_Ynbf[2u * MTOK * CCH];
__device__ __align__(16) __nv_bfloat16 g_Zbf [2u * MTOK * 512];
__device__ __align__(16) __nv_bfloat16 g_Wbf [786432];

// ------------------------- helpers -----------------------------------------
__device__ __forceinline__ uint32_t smem_u32(const void* p) {
    uint32_t a;
    asm("{ .reg .u64 t; cvta.to.shared.u64 t, %1; cvt.u32.u64 %0, t; }" : "=r"(a) : "l"(p));
    return a;
}
__device__ __forceinline__ void mma_bf16(float* c, const uint32_t* a, const uint32_t* b) {
    asm volatile(
        "mma.sync.aligned.m16n8k16.row.col.f32.bf16.bf16.f32 "
        "{%0,%1,%2,%3}, {%4,%5,%6,%7}, {%8,%9}, {%0,%1,%2,%3};"
        : "+f"(c[0]), "+f"(c[1]), "+f"(c[2]), "+f"(c[3])
        : "r"(a[0]), "r"(a[1]), "r"(a[2]), "r"(a[3]), "r"(b[0]), "r"(b[1]));
}
__device__ __forceinline__ void ldm_x4(uint32_t* r, uint32_t addr) {
    asm volatile("ldmatrix.sync.aligned.m8n8.x4.shared.b16 {%0,%1,%2,%3}, [%4];"
                 : "=r"(r[0]), "=r"(r[1]), "=r"(r[2]), "=r"(r[3]) : "r"(addr));
}
__device__ __forceinline__ void ldm_x4_t(uint32_t* r, uint32_t addr) {
    asm volatile("ldmatrix.sync.aligned.m8n8.x4.trans.shared.b16 {%0,%1,%2,%3}, [%4];"
                 : "=r"(r[0]), "=r"(r[1]), "=r"(r[2]), "=r"(r[3]) : "r"(addr));
}
__device__ __forceinline__ uint32_t pack_hi(float x, float y) {
    return (uint32_t)__bfloat16_as_ushort(__float2bfloat16(x)) |
           ((uint32_t)__bfloat16_as_ushort(__float2bfloat16(y)) << 16);
}
__device__ __forceinline__ uint32_t pack_lo(float x, float y) {
    float xh = __bfloat162float(__float2bfloat16(x));
    float yh = __bfloat162float(__float2bfloat16(y));
    return (uint32_t)__bfloat16_as_ushort(__float2bfloat16(x - xh)) |
           ((uint32_t)__bfloat16_as_ushort(__float2bfloat16(y - yh)) << 16);
}
__device__ __forceinline__ void split_bf(float v, __nv_bfloat16& h, __nv_bfloat16& l) {
    h = __float2bfloat16(v);
    l = __float2bfloat16(v - __bfloat162float(h));
}
__device__ __forceinline__ void cpa16(uint32_t d, const void* s) {
    asm volatile("cp.async.ca.shared.global [%0], [%1], 16;"
                 :: "r"(d), "l"(__cvta_generic_to_global(s)) : "memory");
}
#define CPA_COMMIT asm volatile("cp.async.commit_group;" ::: "memory")
#define CPA_WAIT(n) asm volatile("cp.async.wait_group %0;" :: "n"(n) : "memory")

// ---------------------------------------------------------------------------
// Dense GEMM: C[M,N] = A @ W^T. A planes [M,K] (hi, +AMK lo); Wt planes [K,N].
// Tile 128x128x32, double-buffered cp.async. mode 0: fp32 out (+bias,+res).
// mode 1: bf16 planes out (+bias). mode 2: fused LayerNorm (N must be 128):
//   v = acc + bias + res; LN over row; write C=fp32 Yn and Cbf=planes.
// ---------------------------------------------------------------------------
#define RSA 40
#define RSB 136
#define ASZ (128 * RSA * 2)
#define BSZ (32 * RSB * 2)
#define STG (2 * ASZ + 2 * BSZ)
#define GSMEM (2 * STG)

__global__ void __launch_bounds__(256, 2)
gemm_bf(const __nv_bfloat16* __restrict__ A, long long AMK,
        const __nv_bfloat16* __restrict__ Wt, long long WNK,
        int K, int N,
        const float* __restrict__ bias, const float* __restrict__ res,
        float* __restrict__ C, __nv_bfloat16* __restrict__ Cbf, long long CMK,
        int mode, const float* __restrict__ lng, const float* __restrict__ lnb) {
    extern __shared__ char sm[];
    uint32_t sb = smem_u32(sm);
    int tid = threadIdx.x, wid = tid >> 5, l = tid & 31;
    long long bm = (long long)blockIdx.x * 128;
    int bn = blockIdx.y * 128;
    int wm = (wid & 3) * 32, wn = (wid >> 2) * 64;
    int nc = K >> 5;

    auto load_tile = [&](int st, int cc) {
        int k0 = cc << 5;
        uint32_t base = sb + st * STG;
#pragma unroll
        for (int i = tid; i < 1024; i += 256) {
            int pl = i >> 9;
            int r = (i >> 2) & 127;
            int c4 = (i & 3) * 8;
            cpa16(base + pl * ASZ + (r * RSA + c4) * 2,
                  A + pl * AMK + (bm + r) * K + k0 + c4);
        }
#pragma unroll
        for (int i = tid; i < 1024; i += 256) {
            int pl = i >> 9;
            int r = (i >> 4) & 31;
            int c8 = (i & 15) * 8;
            cpa16(base + 2 * ASZ + pl * BSZ + (r * RSB + c8) * 2,
                  Wt + pl * WNK + (size_t)(k0 + r) * N + bn + c8);
        }
    };

    float acc[2][8][4];
#pragma unroll
    for (int a = 0; a < 2; a++)
#pragma unroll
        for (int b = 0; b < 8; b++)
#pragma unroll
            for (int c = 0; c < 4; c++) acc[a][b][c] = 0.f;

    load_tile(0, 0);
    CPA_COMMIT;
    for (int c = 0; c < nc; c++) {
        if (c + 1 < nc) {
            load_tile((c + 1) & 1, c + 1);
            CPA_COMMIT;
            CPA_WAIT(1);
        } else {
            CPA_WAIT(0);
        }
        __syncthreads();
        uint32_t base = sb + (c & 1) * STG;

        uint32_t ah[2][2][4], al[2][2][4];
#pragma unroll
        for (int ks = 0; ks < 2; ks++)
#pragma unroll
            for (int mi = 0; mi < 2; mi++) {
                uint32_t ao = base + ((wm + mi * 16 + (l & 15)) * RSA + ks * 16 + (l >> 4) * 8) * 2;
                ldm_x4(ah[ks][mi], ao);
                ldm_x4(al[ks][mi], ao + ASZ);
            }
#pragma unroll
        for (int nf = 0; nf < 8; nf++) {
            uint32_t bo = base + 2 * ASZ +
                          ((((l >> 3) * 8) + (l & 7)) * RSB + wn + nf * 8) * 2;
            uint32_t bh[4], bl[4];
            ldm_x4_t(bh, bo);
            ldm_x4_t(bl, bo + BSZ);
#pragma unroll
            for (int ks = 0; ks < 2; ks++)
#pragma unroll
                for (int mi = 0; mi < 2; mi++) {
                    mma_bf16(acc[mi][nf], ah[ks][mi], bh + ks * 2);
                    mma_bf16(acc[mi][nf], ah[ks][mi], bl + ks * 2);
                    mma_bf16(acc[mi][nf], al[ks][mi], bh + ks * 2);
                }
        }
        __syncthreads();
    }

    int r0 = wm + (l >> 2);
    if (mode == 2) {
        // ---- fused LayerNorm epilogue (N == 128, bn == 0) ----
        float* tile  = (float*)sm;                // [128][129]
        float* ps    = (float*)(sm + 66048);      // 512 floats
        float* mus   = (float*)(sm + 68096);      // 128
        float* rstds = (float*)(sm + 68608);      // 128
#pragma unroll
        for (int mi = 0; mi < 2; mi++)
#pragma unroll
            for (int half = 0; half < 2; half++) {
                int row = r0 + mi * 16 + half * 8;
#pragma unroll
                for (int nf = 0; nf < 8; nf++) {
                    int col = wn + (l & 3) * 2 + nf * 8;
                    float v0 = acc[mi][nf][half * 2 + 0] + bias[col];
                    float v1 = acc[mi][nf][half * 2 + 1] + bias[col + 1];
                    size_t o = (size_t)(bm + row) * 128 + col;
                    v0 += res[o];
                    v1 += res[o + 1];
                    tile[row * 129 + col] = v0;
                    tile[row * 129 + col + 1] = v1;
                }
            }
        __syncthreads();
        {
            int row = tid & 127, hf = tid >> 7;
            float s = 0.f, q = 0.f;
#pragma unroll 8
            for (int c2 = 0; c2 < 64; c2++) {
                float v = tile[row * 129 + hf * 64 + c2];
                s += v;
                q += v * v;
            }
            ps[tid] = s;
            ps[256 + tid] = q;
        }
        __syncthreads();
        if (tid < 128) {
            float ss = ps[tid] + ps[tid + 128];
            float qq = ps[256 + tid] + ps[256 + tid + 128];
            float mu = ss * (1.0f / 128.0f);
            float var = qq * (1.0f / 128.0f) - mu * mu;
            mus[tid] = mu;
            rstds[tid] = rsqrtf(var + 1e-5f);
        }
        __syncthreads();
        for (int idx = tid; idx < 16384; idx += 256) {
            int r = idx >> 7, c2 = idx & 127;
            float val = (tile[r * 129 + c2] - mus[r]) * rstds[r] * lng[c2] + lnb[c2];
            size_t o = (size_t)(bm + r) * 128 + c2;
            C[o] = val;
            __nv_bfloat16 h, lo2;
            split_bf(val, h, lo2);
            Cbf[o] = h;
            Cbf[CMK + o] = lo2;
        }
        return;
    }

    int cb = bn + wn + (l & 3) * 2;
#pragma unroll
    for (int mi = 0; mi < 2; mi++) {
#pragma unroll
        for (int half = 0; half < 2; half++) {
            long long row = bm + r0 + mi * 16 + half * 8;
#pragma unroll
            for (int nf = 0; nf < 8; nf++) {
                int col = cb + nf * 8;
                float v0 = acc[mi][nf][half * 2 + 0];
                float v1 = acc[mi][nf][half * 2 + 1];
                if (bias) { v0 += bias[col]; v1 += bias[col + 1]; }
                size_t o = (size_t)row * N + col;
                if (mode == 1) {
                    __nv_bfloat16 h0, l0, h1, l1;
                    split_bf(v0, h0, l0);
                    split_bf(v1, h1, l1);
                    __nv_bfloat162 hh; hh.x = h0; hh.y = h1;
                    __nv_bfloat162 ll; ll.x = l0; ll.y = l1;
                    *(__nv_bfloat162*)(Cbf + o) = hh;
                    *(__nv_bfloat162*)(Cbf + CMK + o) = ll;
                } else {
                    if (res) { v0 += res[o]; v1 += res[o + 1]; }
                    *(float2*)(C + o) = make_float2(v0, v1);
                }
            }
        }
    }
}

// ---------------------------------------------------------------------------
// Stage-2 flash attention (bf16-plane QKV in, bf16-plane O out).
// ---------------------------------------------------------------------------
#define FQH 0
#define FKH 20480
#define FVH 40960
#define FBIAS 61440
#define FSMEM (61440 + 3969 * 4)

__global__ void __launch_bounds__(256)
flash2(const __nv_bfloat16* __restrict__ QKVbf, const float* __restrict__ table,
       __nv_bfloat16* __restrict__ Obf) {
    extern __shared__ char fsm[];
    uint32_t sb = smem_u32(fsm);
    float* sBias = (float*)(fsm + FBIAS);

    int tid = threadIdx.x, wid = tid >> 5, ln = tid & 31;
    int bh = blockIdx.y, b = bh >> 2, h = bh & 3;
    int bq = blockIdx.x * 128;
    const long long QMK = (long long)MTOK * 384;
    const long long OMK = (long long)MTOK * 128;
    long long tok0 = (long long)b * 1024;

    for (int i = tid; i < 3969; i += 256) sBias[i] = table[i * 4 + h];

#pragma unroll
    for (int i = tid; i < 1024; i += 256) {
        int pl = i >> 9, r = (i >> 2) & 127, c4 = (i & 3) * 8;
        cpa16(sb + FQH + pl * 10240 + (r * RSA + c4) * 2,
              QKVbf + pl * QMK + (tok0 + bq + r) * 384 + h * 32 + c4);
    }
    CPA_COMMIT;
    CPA_WAIT(0);
    __syncthreads();

    int rbase = wid * 16;
    uint32_t qh[2][4], ql[2][4];
#pragma unroll
    for (int ks = 0; ks < 2; ks++) {
        uint32_t ao = sb + FQH + ((rbase + (ln & 15)) * RSA + ks * 16 + (ln >> 4) * 8) * 2;
        ldm_x4(qh[ks], ao);
        ldm_x4(ql[ks], ao + 10240);
    }

    float oacc[4][4];
#pragma unroll
    for (int i = 0; i < 4; i++)
#pragma unroll
        for (int j = 0; j < 4; j++) oacc[i][j] = 0.f;
    float m0 = -1e30f, m1 = -1e30f, ls0 = 0.f, ls1 = 0.f;

    int n0 = bq + rbase + (ln >> 2);
    int n1 = n0 + 8;
    int i1a = n0 >> 5, j1a = n0 & 31;
    int i1b = n1 >> 5, j1b = n1 & 31;
    int mcb = 2 * (ln & 3);
    const float SC = 5.656854249492381f;

    for (int kt = 0; kt < 8; kt++) {
#pragma unroll
        for (int i = tid; i < 2048; i += 256) {
            int tensor = i >> 10;
            int pl = (i >> 9) & 1;
            int r = (i >> 2) & 127, c4 = (i & 3) * 8;
            cpa16(sb + FKH + tensor * 20480 + pl * 10240 + (r * RSA + c4) * 2,
                  QKVbf + pl * QMK + (tok0 + kt * 128 + r) * 384 + 128 + tensor * 128 + h * 32 + c4);
        }
        CPA_COMMIT;
        CPA_WAIT(0);
        __syncthreads();

        float sa[16][4];
#pragma unroll
        for (int nf = 0; nf < 16; nf++) {
            sa[nf][0] = sa[nf][1] = sa[nf][2] = sa[nf][3] = 0.f;
            uint32_t bh4[4], bl4[4];
            uint32_t bo = sb + FKH + ((nf * 8 + (ln & 7)) * RSA + (ln >> 3) * 8) * 2;
            ldm_x4(bh4, bo);
            ldm_x4(bl4, bo + 10240);
            mma_bf16(sa[nf], qh[0], bh4 + 0);
            mma_bf16(sa[nf], qh[1], bh4 + 2);
            mma_bf16(sa[nf], qh[0], bl4 + 0);
            mma_bf16(sa[nf], qh[1], bl4 + 2);
            mma_bf16(sa[nf], ql[0], bh4 + 0);
            mma_bf16(sa[nf], ql[1], bh4 + 2);
        }

        float mx0 = -1e30f, mx1 = -1e30f;
#pragma unroll
        for (int nf = 0; nf < 16; nf++) {
            int mc = kt * 128 + nf * 8 + mcb;
            int i2a = mc >> 5, j2a = mc & 31;
            int i2b = (mc + 1) >> 5, j2b = (mc + 1) & 31;
            float s0 = sa[nf][0] * SC + sBias[(i1a - i2a + 31) * 63 + (j1a - j2a + 31)];
            float s1 = sa[nf][1] * SC + sBias[(i1a - i2b + 31) * 63 + (j1a - j2b + 31)];
            float s2 = sa[nf][2] * SC + sBias[(i1b - i2a + 31) * 63 + (j1b - j2a + 31)];
            float s3 = sa[nf][3] * SC + sBias[(i1b - i2b + 31) * 63 + (j1b - j2b + 31)];
            sa[nf][0] = s0; sa[nf][1] = s1; sa[nf][2] = s2; sa[nf][3] = s3;
            mx0 = fmaxf(mx0, fmaxf(s0, s1));
            mx1 = fmaxf(mx1, fmaxf(s2, s3));
        }
        mx0 = fmaxf(mx0, __shfl_xor_sync(0xffffffffu, mx0, 1));
        mx0 = fmaxf(mx0, __shfl_xor_sync(0xffffffffu, mx0, 2));
        mx1 = fmaxf(mx1, __shfl_xor_sync(0xffffffffu, mx1, 1));
        mx1 = fmaxf(mx1, __shfl_xor_sync(0xffffffffu, mx1, 2));
        float mn0 = fmaxf(m0, mx0), mn1 = fmaxf(m1, mx1);
        float f0 = __expf(m0 - mn0), f1 = __expf(m1 - mn1);

        float su0 = 0.f, su1 = 0.f;
#pragma unroll
        for (int nf = 0; nf < 16; nf++) {
            float p0 = __expf(sa[nf][0] - mn0);
            float p1 = __expf(sa[nf][1] - mn0);
            float p2 = __expf(sa[nf][2] - mn1);
            float p3 = __expf(sa[nf][3] - mn1);
            sa[nf][0] = p0; sa[nf][1] = p1; sa[nf][2] = p2; sa[nf][3] = p3;
            su0 += p0 + p1; su1 += p2 + p3;
        }
        su0 += __shfl_xor_sync(0xffffffffu, su0, 1);
        su0 += __shfl_xor_sync(0xffffffffu, su0, 2);
        su1 += __shfl_xor_sync(0xffffffffu, su1, 1);
        su1 += __shfl_xor_sync(0xffffffffu, su1, 2);
        ls0 = ls0 * f0 + su0;
        ls1 = ls1 * f1 + su1;
        m0 = mn0; m1 = mn1;

#pragma unroll
        for (int nd = 0; nd < 4; nd++) {
            oacc[nd][0] *= f0; oacc[nd][1] *= f0;
            oacc[nd][2] *= f1; oacc[nd][3] *= f1;
        }

#pragma unroll
        for (int ks2 = 0; ks2 < 4; ks2++) {
            int k0 = ks2 * 32;
            uint32_t pa0h[4], pa0l[4], pa1h[4], pa1l[4];
            int nfa = 4 * ks2, nfb = nfa + 1, nfc = nfa + 2, nfd = nfa + 3;
            pa0h[0] = pack_hi(sa[nfa][0], sa[nfa][1]);
            pa0h[1] = pack_hi(sa[nfa][2], sa[nfa][3]);
            pa0h[2] = pack_hi(sa[nfb][0], sa[nfb][1]);
            pa0h[3] = pack_hi(sa[nfb][2], sa[nfb][3]);
            pa0l[0] = pack_lo(sa[nfa][0], sa[nfa][1]);
            pa0l[1] = pack_lo(sa[nfa][2], sa[nfa][3]);
            pa0l[2] = pack_lo(sa[nfb][0], sa[nfb][1]);
            pa0l[3] = pack_lo(sa[nfb][2], sa[nfb][3]);
            pa1h[0] = pack_hi(sa[nfc][0], sa[nfc][1]);
            pa1h[1] = pack_hi(sa[nfc][2], sa[nfc][3]);
            pa1h[2] = pack_hi(sa[nfd][0], sa[nfd][1]);
            pa1h[3] = pack_hi(sa[nfd][2], sa[nfd][3]);
            pa1l[0] = pack_lo(sa[nfc][0], sa[nfc][1]);
            pa1l[1] = pack_lo(sa[nfc][2], sa[nfc][3]);
            pa1l[2] = pack_lo(sa[nfd][0], sa[nfd][1]);
            pa1l[3] = pack_lo(sa[nfd][2], sa[nfd][3]);
#pragma unroll
            for (int nd = 0; nd < 4; nd++) {
                uint32_t vh4[4], vl4[4];
                uint32_t vo = sb + FVH + ((k0 + (ln >> 3) * 8 + (ln & 7)) * RSA + nd * 8) * 2;
                ldm_x4_t(vh4, vo);
                ldm_x4_t(vl4, vo + 10240);
                mma_bf16(oacc[nd], pa0h, vh4 + 0);
                mma_bf16(oacc[nd], pa1h, vh4 + 2);
                mma_bf16(oacc[nd], pa0h, vl4 + 0);
                mma_bf16(oacc[nd], pa1h, vl4 + 2);
                mma_bf16(oacc[nd], pa0l, vh4 + 0);
                mma_bf16(oacc[nd], pa1l, vh4 + 2);
            }
        }
        __syncthreads();
    }

    float inv0 = 1.0f / ls0, inv1 = 1.0f / ls1;
    size_t o0 = (size_t)(tok0 + n0) * 128 + h * 32;
    size_t o1 = (size_t)(tok0 + n1) * 128 + h * 32;
#pragma unroll
    for (int nd = 0; nd < 4; nd++) {
        int d = nd * 8 + mcb;
        float a0 = oacc[nd][0] * inv0, a1 = oacc[nd][1] * inv0;
        float b0 = oacc[nd][2] * inv1, b1 = oacc[nd][3] * inv1;
        __nv_bfloat16 h0, l0, h1, l1;
        split_bf(a0, h0, l0); split_bf(a1, h1, l1);
        __nv_bfloat162 hh; hh.x = h0; hh.y = h1;
        __nv_bfloat162 ll; ll.x = l0; ll.y = l1;
        *(__nv_bfloat162*)(Obf + o0 + d) = hh;
        *(__nv_bfloat162*)(Obf + OMK + o0 + d) = ll;
        split_bf(b0, h0, l0); split_bf(b1, h1, l1);
        hh.x = h0; hh.y = h1; ll.x = l0; ll.y = l1;
        *(__nv_bfloat162*)(Obf + o1 + d) = hh;
        *(__nv_bfloat162*)(Obf + OMK + o1 + d) = ll;
    }
}

// ---------------------------------------------------------------------------
// Stage-1 attention on tensor cores: one block per (window,head). N=49 padded
// to 64; cols >=49 masked to -inf; padded rows clamped (outputs not written).
// ---------------------------------------------------------------------------
#define ASQ 0
#define ASK 10240
#define ASV 20480
#define ASB 30720

__global__ void __launch_bounds__(128)
attn_small_tc(const __nv_bfloat16* __restrict__ QKVbf, const float* __restrict__ table,
              __nv_bfloat16* __restrict__ Obf) {
    __shared__ __align__(16) char sm1[31424];
    uint32_t sb = smem_u32(sm1);
    float* sT = (float*)(sm1 + ASB);

    int tid = threadIdx.x, wid = tid >> 5, ln = tid & 31;
    int bh = blockIdx.x, b = bh >> 2, h = bh & 3;
    const long long QMK = (long long)MTOK * 384;
    const long long OMK = (long long)MTOK * 128;
    long long tokb = (long long)b * 49;

    for (int i = tid; i < 169; i += 128) sT[i] = table[i * 4 + h];
#pragma unroll
    for (int i = tid; i < 1536; i += 128) {
        int tensor = i / 512;
        int pl = (i >> 8) & 1;
        int r = (i >> 2) & 63;
        int c4 = (i & 3) * 8;
        int rc = r < 49 ? r : 48;
        cpa16(sb + tensor * 10240 + pl * 5120 + (r * RSA + c4) * 2,
              QKVbf + pl * QMK + (tokb + rc) * 384 + tensor * 128 + h * 32 + c4);
    }
    CPA_COMMIT;
    CPA_WAIT(0);
    __syncthreads();

    uint32_t qh[2][4], ql[2][4];
#pragma unroll
    for (int ks = 0; ks < 2; ks++) {
        uint32_t ao = sb + ASQ + ((wid * 16 + (ln & 15)) * RSA + ks * 16 + (ln >> 4) * 8) * 2;
        ldm_x4(qh[ks], ao);
        ldm_x4(ql[ks], ao + 5120);
    }

    // S = Q K^T (16 rows x 64 cols per warp)
    float sa[8][4];
#pragma unroll
    for (int nf = 0; nf < 8; nf++) {
        sa[nf][0] = sa[nf][1] = sa[nf][2] = sa[nf][3] = 0.f;
        uint32_t bh4[4], bl4[4];
        uint32_t bo = sb + ASK + ((nf * 8 + (ln & 7)) * RSA + (ln >> 3) * 8) * 2;
        ldm_x4(bh4, bo);
        ldm_x4(bl4, bo + 5120);
        mma_bf16(sa[nf], qh[0], bh4 + 0);
        mma_bf16(sa[nf], qh[1], bh4 + 2);
        mma_bf16(sa[nf], qh[0], bl4 + 0);
        mma_bf16(sa[nf], qh[1], bl4 + 2);
        mma_bf16(sa[nf], ql[0], bh4 + 0);
        mma_bf16(sa[nf], ql[1], bh4 + 2);
    }

    int n0 = wid * 16 + (ln >> 2);
    int n1 = n0 + 8;
    int n0c = n0 < 49 ? n0 : 48;
    int n1c = n1 < 49 ? n1 : 48;
    int i1a = n0c / 7, j1a = n0c % 7;
    int i1b = n1c / 7, j1b = n1c % 7;
    int mcb = 2 * (ln & 3);
    const float SC = 5.656854249492381f;

    float mx0 = -1e30f, mx1 = -1e30f;
#pragma unroll
    for (int nf = 0; nf < 8; nf++) {
        int mc = nf * 8 + mcb;
        float s0, s1, s2, s3;
        if (mc < 49) {
            int i2 = mc / 7, j2 = mc % 7;
            s0 = sa[nf][0] * SC + sT[(i1a - i2 + 6) * 13 + (j1a - j2 + 6)];
            s2 = sa[nf][2] * SC + sT[(i1b - i2 + 6) * 13 + (j1b - j2 + 6)];
        } else { s0 = -1e30f; s2 = -1e30f; }
        if (mc + 1 < 49) {
            int i2 = (mc + 1) / 7, j2 = (mc + 1) % 7;
            s1 = sa[nf][1] * SC + sT[(i1a - i2 + 6) * 13 + (j1a - j2 + 6)];
            s3 = sa[nf][3] * SC + sT[(i1b - i2 + 6) * 13 + (j1b - j2 + 6)];
        } else { s1 = -1e30f; s3 = -1e30f; }
        sa[nf][0] = s0; sa[nf][1] = s1; sa[nf][2] = s2; sa[nf][3] = s3;
        mx0 = fmaxf(mx0, fmaxf(s0, s1));
        mx1 = fmaxf(mx1, fmaxf(s2, s3));
    }
    mx0 = fmaxf(mx0, __shfl_xor_sync(0xffffffffu, mx0, 1));
    mx0 = fmaxf(mx0, __shfl_xor_sync(0xffffffffu, mx0, 2));
    mx1 = fmaxf(mx1, __shfl_xor_sync(0xffffffffu, mx1, 1));
    mx1 = fmaxf(mx1, __shfl_xor_sync(0xffffffffu, mx1, 2));

    float ls0 = 0.f, ls1 = 0.f;
#pragma unroll
    for (int nf = 0; nf < 8; nf++) {
        float p0 = __expf(sa[nf][0] - mx0);
        float p1 = __expf(sa[nf][1] - mx0);
        float p2 = __expf(sa[nf][2] - mx1);
        float p3 = __expf(sa[nf][3] - mx1);
        sa[nf][0] = p0; sa[nf][1] = p1; sa[nf][2] = p2; sa[nf][3] = p3;
        ls0 += p0 + p1; ls1 += p2 + p3;
    }
    ls0 += __shfl_xor_sync(0xffffffffu, ls0, 1);
    ls0 += __shfl_xor_sync(0xffffffffu, ls0, 2);
    ls1 += __shfl_xor_sync(0xffffffffu, ls1, 1);
    ls1 += __shfl_xor_sync(0xffffffffu, ls1, 2);

    // O = P V
    float oacc[4][4];
#pragma unroll
    for (int i = 0; i < 4; i++)
#pragma unroll
        for (int j = 0; j < 4; j++) oacc[i][j] = 0.f;
#pragma unroll
    for (int ks2 = 0; ks2 < 2; ks2++) {
        int k0 = ks2 * 32;
        uint32_t pa0h[4], pa0l[4], pa1h[4], pa1l[4];
        int nfa = 4 * ks2, nfb = nfa + 1, nfc = nfa + 2, nfd = nfa + 3;
        pa0h[0] = pack_hi(sa[nfa][0], sa[nfa][1]);
        pa0h[1] = pack_hi(sa[nfa][2], sa[nfa][3]);
        pa0h[2] = pack_hi(sa[nfb][0], sa[nfb][1]);
        pa0h[3] = pack_hi(sa[nfb][2], sa[nfb][3]);
        pa0l[0] = pack_lo(sa[nfa][0], sa[nfa][1]);
        pa0l[1] = pack_lo(sa[nfa][2], sa[nfa][3]);
        pa0l[2] = pack_lo(sa[nfb][0], sa[nfb][1]);
        pa0l[3] = pack_lo(sa[nfb][2], sa[nfb][3]);
        pa1h[0] = pack_hi(sa[nfc][0], sa[nfc][1]);
        pa1h[1] = pack_hi(sa[nfc][2], sa[nfc][3]);
        pa1h[2] = pack_hi(sa[nfd][0], sa[nfd][1]);
        pa1h[3] = pack_hi(sa[nfd][2], sa[nfd][3]);
        pa1l[0] = pack_lo(sa[nfc][0], sa[nfc][1]);
        pa1l[1] = pack_lo(sa[nfc][2], sa[nfc][3]);
        pa1l[2] = pack_lo(sa[nfd][0], sa[nfd][1]);
        pa1l[3] = pack_lo(sa[nfd][2], sa[nfd][3]);
#pragma unroll
        for (int nd = 0; nd < 4; nd++) {
            uint32_t vh4[4], vl4[4];
            uint32_t vo = sb + ASV + ((k0 + (ln >> 3) * 8 + (ln & 7)) * RSA + nd * 8) * 2;
            ldm_x4_t(vh4, vo);
            ldm_x4_t(vl4, vo + 5120);
            mma_bf16(oacc[nd], pa0h, vh4 + 0);
            mma_bf16(oacc[nd], pa1h, vh4 + 2);
            mma_bf16(oacc[nd], pa0h, vl4 + 0);
            mma_bf16(oacc[nd], pa1h, vl4 + 2);
            mma_bf16(oacc[nd], pa0l, vh4 + 0);
            mma_bf16(oacc[nd], pa1l, vh4 + 2);
        }
    }

    float inv0 = 1.0f / ls0, inv1 = 1.0f / ls1;
#pragma unroll
    for (int nd = 0; nd < 4; nd++) {
        int d = nd * 8 + mcb;
        if (n0 < 49) {
            size_t o0 = (size_t)(tokb + n0) * 128 + h * 32 + d;
            __nv_bfloat16 h0, l0, h1, l1;
            split_bf(oacc[nd][0] * inv0, h0, l0);
            split_bf(oacc[nd][1] * inv0, h1, l1);
            __nv_bfloat162 hh; hh.x = h0; hh.y = h1;
            __nv_bfloat162 ll; ll.x = l0; ll.y = l1;
            *(__nv_bfloat162*)(Obf + o0) = hh;
            *(__nv_bfloat162*)(Obf + OMK + o0) = ll;
        }
        if (n1 < 49) {
            size_t o1 = (size_t)(tokb + n1) * 128 + h * 32 + d;
            __nv_bfloat16 h0, l0, h1, l1;
            split_bf(oacc[nd][2] * inv1, h0, l0);
            split_bf(oacc[nd][3] * inv1, h1, l1);
            __nv_bfloat162 hh; hh.x = h0; hh.y = h1;
            __nv_bfloat162 ll; ll.x = l0; ll.y = l1;
            *(__nv_bfloat162*)(Obf + o1) = hh;
            *(__nv_bfloat162*)(Obf + OMK + o1) = ll;
        }
    }
}

// ------------------------- permutations ------------------------------------
// Coalesced window partition: tiles of 32 channels x 64 spatial via smem.
__global__ void __launch_bounds__(256)
winpart_tile(const float* __restrict__ x, float* __restrict__ X,
             __nv_bfloat16* __restrict__ Xbf) {
    __shared__ float tile[32][65];
    const long long XMK = (long long)MTOK * 128;
    int sp0 = blockIdx.x * 64;
    int c0 = blockIdx.y * 32;
    int tid = threadIdx.x;
    {
        int ci = tid >> 3, si = (tid & 7) * 8;
        const float* p = x + (size_t)(c0 + ci) * MTOK + sp0 + si;
        float4 u0 = *(const float4*)p;
        float4 u1 = *(const float4*)(p + 4);
        tile[ci][si + 0] = u0.x; tile[ci][si + 1] = u0.y;
        tile[ci][si + 2] = u0.z; tile[ci][si + 3] = u0.w;
        tile[ci][si + 4] = u1.x; tile[ci][si + 5] = u1.y;
        tile[ci][si + 6] = u1.z; tile[ci][si + 7] = u1.w;
    }
    __syncthreads();
    {
        int si = tid >> 2, cj = (tid & 3) * 8;
        int sp = sp0 + si;
        int hh = sp / HWDIM, ww = sp % HWDIM;
        int out_t = ((hh / 7) * 32 + (ww / 7)) * 49 + (hh % 7) * 7 + (ww % 7);
        size_t ob = (size_t)out_t * 128 + c0 + cj;
#pragma unroll
        for (int k = 0; k < 8; k++) {
            float v = tile[cj + k][si];
            X[ob + k] = v;
            __nv_bfloat16 h, l;
            split_bf(v, h, l);
            Xbf[ob + k] = h;
            Xbf[XMK + ob + k] = l;
        }
    }
}
__global__ void permute_b2g_kernel(const float* __restrict__ A, float* __restrict__ Xg,
                                   __nv_bfloat16* __restrict__ Xbf) {
    const long long XMK = (long long)MTOK * 128;
    int idx = blockIdx.x * 256 + threadIdx.x;
    if (idx >= MTOK * CCH) return;
    int cg = idx & 127;
    int t = idx >> 7;
    int tok = t & 1023;
    int win = t >> 10;
    int gho = win / 7, gwo = win % 7;
    int ghi = tok >> 5, gwi = tok & 31;
    int h2 = gho * 32 + ghi, w2 = gwo * 32 + gwi;
    int f = (h2 * HWDIM + w2) * CCH + cg;
    int wo = f & 31; f >>= 5;
    int wi = f % 7;  f /= 7;
    int hi2 = f % 7; f /= 7;
    int ho = f & 31; f >>= 5;
    int c = f;
    float v = A[((ho * 32 + wo) * 49 + (hi2 * 7 + wi)) * CCH + c];
    Xg[idx] = v;
    __nv_bfloat16 h, l;
    split_bf(v, h, l);
    Xbf[idx] = h;
    Xbf[XMK + idx] = l;
}
__global__ void permute_g2out_kernel(const float* __restrict__ A, float* __restrict__ out) {
    int idx = blockIdx.x * 256 + threadIdx.x;
    if (idx >= MTOK * CCH) return;
    int w2 = idx % HWDIM;
    int t = idx / HWDIM;
    int h2 = t % HWDIM;
    int c2 = t / HWDIM;
    int f = (h2 * HWDIM + w2) * CCH + c2;
    int gwo = f % 7;  f /= 7;
    int gwi = f & 31; f >>= 5;
    int ghi = f & 31; f >>= 5;
    int gho = f % 7;  f /= 7;
    int c = f;
    out[idx] = A[((gho * 7 + gwo) * 1024 + ghi * 32 + gwi) * CCH + c];
}

// ------------------------- weight pre-split (all 8, one launch) -------------
struct WParams {
    const float* src[8];
    __nv_bfloat16* dst[8];
    int N[8];
    int K[8];
};
__global__ void convw8(WParams p) {
    int w = blockIdx.y;
    int N = p.N[w], K = p.K[w];
    int NK = N * K;
    const float* src = p.src[w];
    __nv_bfloat16* dst = p.dst[w];
    for (int idx = blockIdx.x * 256 + threadIdx.x; idx < NK; idx += gridDim.x * 256) {
        int n = idx / K, k = idx % K;
        float v = src[idx];
        __nv_bfloat16 h, l;
        split_bf(v, h, l);
        dst[(size_t)k * N + n] = h;
        dst[(size_t)NK + (size_t)k * N + n] = l;
    }
}

// ------------------------- host orchestration -------------------------------
extern "C" void kernel_launch(void* const* d_in, const int* in_sizes, int n_in,
                              void* d_out, int out_size) {
    const float* x = (const float*)d_in[0];
    const float* bp[10];
    const float* gp[10];
    for (int i = 0; i < 10; i++) bp[i] = (const float*)d_in[1 + i];
    for (int i = 0; i < 10; i++) gp[i] = (const float*)d_in[11 + i];

    cudaFuncSetAttribute(gemm_bf, cudaFuncAttributeMaxDynamicSharedMemorySize, GSMEM);
    cudaFuncSetAttribute(flash2, cudaFuncAttributeMaxDynamicSharedMemorySize, FSMEM);

    float *X, *Yn, *Out;
    __nv_bfloat16 *Xbf, *QKVbf, *Obf, *Ynbf, *Zbf, *Wbf;
    cudaGetSymbolAddress((void**)&X, g_X);
    cudaGetSymbolAddress((void**)&Yn, g_Yn);
    cudaGetSymbolAddress((void**)&Out, g_Out);
    cudaGetSymbolAddress((void**)&Xbf, g_Xbf);
    cudaGetSymbolAddress((void**)&QKVbf, g_QKVbf);
    cudaGetSymbolAddress((void**)&Obf, g_Obf);
    cudaGetSymbolAddress((void**)&Ynbf, g_Ynbf);
    cudaGetSymbolAddress((void**)&Zbf, g_Zbf);
    cudaGetSymbolAddress((void**)&Wbf, g_Wbf);

    const long long XMK = (long long)MTOK * 128;
    const long long QMK = (long long)MTOK * 384;
    const long long ZMK = (long long)MTOK * 512;
    const int nblk = (MTOK * CCH + 255) / 256;

    // ---- weight pre-split, single launch ----
    WParams wp;
    wp.src[0] = bp[1]; wp.dst[0] = Wbf + 0;      wp.N[0] = 384; wp.K[0] = 128;
    wp.src[1] = bp[2]; wp.dst[1] = Wbf + 98304;  wp.N[1] = 128; wp.K[1] = 128;
    wp.src[2] = bp[6]; wp.dst[2] = Wbf + 131072; wp.N[2] = 512; wp.K[2] = 128;
    wp.src[3] = bp[8]; wp.dst[3] = Wbf + 262144; wp.N[3] = 128; wp.K[3] = 512;
    wp.src[4] = gp[1]; wp.dst[4] = Wbf + 393216; wp.N[4] = 384; wp.K[4] = 128;
    wp.src[5] = gp[2]; wp.dst[5] = Wbf + 491520; wp.N[5] = 128; wp.K[5] = 128;
    wp.src[6] = gp[6]; wp.dst[6] = Wbf + 524288; wp.N[6] = 512; wp.K[6] = 128;
    wp.src[7] = gp[8]; wp.dst[7] = Wbf + 655360; wp.N[7] = 128; wp.K[7] = 512;
    convw8<<<dim3(64, 8), 256>>>(wp);

    // ================= Stage 1: 7x7 windows ==================
    winpart_tile<<<dim3(MTOK / 64, 4), 256>>>(x, X, Xbf);
    gemm_bf<<<dim3(392, 3), 256, GSMEM>>>(Xbf, XMK, Wbf + 0, 49152, 128, 384,
                                          nullptr, nullptr, nullptr, QKVbf, QMK, 1, nullptr, nullptr);
    attn_small_tc<<<4096, 128>>>(QKVbf, bp[0], Obf);
    gemm_bf<<<dim3(392, 1), 256, GSMEM>>>(Obf, XMK, Wbf + 98304, 16384, 128, 128,
                                          bp[3], X, Yn, Ynbf, XMK, 2, bp[4], bp[5]);
    gemm_bf<<<dim3(392, 4), 256, GSMEM>>>(Ynbf, XMK, Wbf + 131072, 65536, 128, 512,
                                          bp[7], nullptr, nullptr, Zbf, ZMK, 1, nullptr, nullptr);
    gemm_bf<<<dim3(392, 1), 256, GSMEM>>>(Zbf, ZMK, Wbf + 262144, 65536, 512, 128,
                                          bp[9], Yn, Out, nullptr, 0, 0, nullptr, nullptr);

    permute_b2g_kernel<<<nblk, 256>>>(Out, X, Xbf);

    // ================= Stage 2: 32x32 grid ===================
    gemm_bf<<<dim3(392, 3), 256, GSMEM>>>(Xbf, XMK, Wbf + 393216, 49152, 128, 384,
                                          nullptr, nullptr, nullptr, QKVbf, QMK, 1, nullptr, nullptr);
    flash2<<<dim3(8, 196), 256, FSMEM>>>(QKVbf, gp[0], Obf);
    gemm_bf<<<dim3(392, 1), 256, GSMEM>>>(Obf, XMK, Wbf + 491520, 16384, 128, 128,
                                          gp[3], X, Yn, Ynbf, XMK, 2, gp[4], gp[5]);
    gemm_bf<<<dim3(392, 4), 256, GSMEM>>>(Ynbf, XMK, Wbf + 524288, 65536, 128, 512,
                                          gp[7], nullptr, nullptr, Zbf, ZMK, 1, nullptr, nullptr);
    gemm_bf<<<dim3(392, 1), 256, GSMEM>>>(Zbf, ZMK, Wbf + 655360, 65536, 512, 128,
                                          gp[9], Yn, Out, nullptr, 0, 0, nullptr, nullptr);

    permute_g2out_kernel<<<nblk, 256>>>(Out, (float*)d_out);
}

// round 7
// speedup vs baseline: 4.0880x; 1.0106x over previous
#include <cuda_runtime.h>
#include <cuda_bf16.h>
#include <stdint.h>

// ---------------------------------------------------------------------------
// MaxSA R6: double-buffered flash2 KV pipeline; fully-coalesced b2g permute;
// vectorized g2out. LN stays fused in proj GEMM; stage1 attention on TC.
// ---------------------------------------------------------------------------

#define CCH   128
#define HWDIM 224
#define MTOK  50176

__device__ __align__(16) float g_X  [MTOK * CCH];
__device__ __align__(16) float g_Yn [MTOK * CCH];
__device__ __align__(16) float g_Out[MTOK * CCH];
__device__ __align__(16) __nv_bfloat16 g_Xbf [2u * MTOK * CCH];
__device__ __align__(16) __nv_bfloat16 g_QKVbf[2u * MTOK * 384];
__device__ __align__(16) __nv_bfloat16 g_Obf [2u * MTOK * CCH];
__device__ __align__(16) __nv_bfloat16 g_Ynbf[2u * MTOK * CCH];
__device__ __align__(16) __nv_bfloat16 g_Zbf [2u * MTOK * 512];
__device__ __align__(16) __nv_bfloat16 g_Wbf [786432];

// ------------------------- helpers -----------------------------------------
__device__ __forceinline__ uint32_t smem_u32(const void* p) {
    uint32_t a;
    asm("{ .reg .u64 t; cvta.to.shared.u64 t, %1; cvt.u32.u64 %0, t; }" : "=r"(a) : "l"(p));
    return a;
}
__device__ __forceinline__ void mma_bf16(float* c, const uint32_t* a, const uint32_t* b) {
    asm volatile(
        "mma.sync.aligned.m16n8k16.row.col.f32.bf16.bf16.f32 "
        "{%0,%1,%2,%3}, {%4,%5,%6,%7}, {%8,%9}, {%0,%1,%2,%3};"
        : "+f"(c[0]), "+f"(c[1]), "+f"(c[2]), "+f"(c[3])
        : "r"(a[0]), "r"(a[1]), "r"(a[2]), "r"(a[3]), "r"(b[0]), "r"(b[1]));
}
__device__ __forceinline__ void ldm_x4(uint32_t* r, uint32_t addr) {
    asm volatile("ldmatrix.sync.aligned.m8n8.x4.shared.b16 {%0,%1,%2,%3}, [%4];"
                 : "=r"(r[0]), "=r"(r[1]), "=r"(r[2]), "=r"(r[3]) : "r"(addr));
}
__device__ __forceinline__ void ldm_x4_t(uint32_t* r, uint32_t addr) {
    asm volatile("ldmatrix.sync.aligned.m8n8.x4.trans.shared.b16 {%0,%1,%2,%3}, [%4];"
                 : "=r"(r[0]), "=r"(r[1]), "=r"(r[2]), "=r"(r[3]) : "r"(addr));
}
__device__ __forceinline__ uint32_t pack_hi(float x, float y) {
    return (uint32_t)__bfloat16_as_ushort(__float2bfloat16(x)) |
           ((uint32_t)__bfloat16_as_ushort(__float2bfloat16(y)) << 16);
}
__device__ __forceinline__ uint32_t pack_lo(float x, float y) {
    float xh = __bfloat162float(__float2bfloat16(x));
    float yh = __bfloat162float(__float2bfloat16(y));
    return (uint32_t)__bfloat16_as_ushort(__float2bfloat16(x - xh)) |
           ((uint32_t)__bfloat16_as_ushort(__float2bfloat16(y - yh)) << 16);
}
__device__ __forceinline__ void split_bf(float v, __nv_bfloat16& h, __nv_bfloat16& l) {
    h = __float2bfloat16(v);
    l = __float2bfloat16(v - __bfloat162float(h));
}
__device__ __forceinline__ void cpa16(uint32_t d, const void* s) {
    asm volatile("cp.async.ca.shared.global [%0], [%1], 16;"
                 :: "r"(d), "l"(__cvta_generic_to_global(s)) : "memory");
}
#define CPA_COMMIT asm volatile("cp.async.commit_group;" ::: "memory")
#define CPA_WAIT(n) asm volatile("cp.async.wait_group %0;" :: "n"(n) : "memory")

// ---------------------------------------------------------------------------
// Dense GEMM: C[M,N] = A @ W^T. A planes [M,K] (hi, +AMK lo); Wt planes [K,N].
// Tile 128x128x32, double-buffered cp.async. mode 0: fp32 out (+bias,+res).
// mode 1: bf16 planes out (+bias). mode 2: fused LayerNorm (N == 128).
// ---------------------------------------------------------------------------
#define RSA 40
#define RSB 136
#define ASZ (128 * RSA * 2)
#define BSZ (32 * RSB * 2)
#define STG (2 * ASZ + 2 * BSZ)
#define GSMEM (2 * STG)

__global__ void __launch_bounds__(256, 2)
gemm_bf(const __nv_bfloat16* __restrict__ A, long long AMK,
        const __nv_bfloat16* __restrict__ Wt, long long WNK,
        int K, int N,
        const float* __restrict__ bias, const float* __restrict__ res,
        float* __restrict__ C, __nv_bfloat16* __restrict__ Cbf, long long CMK,
        int mode, const float* __restrict__ lng, const float* __restrict__ lnb) {
    extern __shared__ char sm[];
    uint32_t sb = smem_u32(sm);
    int tid = threadIdx.x, wid = tid >> 5, l = tid & 31;
    long long bm = (long long)blockIdx.x * 128;
    int bn = blockIdx.y * 128;
    int wm = (wid & 3) * 32, wn = (wid >> 2) * 64;
    int nc = K >> 5;

    auto load_tile = [&](int st, int cc) {
        int k0 = cc << 5;
        uint32_t base = sb + st * STG;
#pragma unroll
        for (int i = tid; i < 1024; i += 256) {
            int pl = i >> 9;
            int r = (i >> 2) & 127;
            int c4 = (i & 3) * 8;
            cpa16(base + pl * ASZ + (r * RSA + c4) * 2,
                  A + pl * AMK + (bm + r) * K + k0 + c4);
        }
#pragma unroll
        for (int i = tid; i < 1024; i += 256) {
            int pl = i >> 9;
            int r = (i >> 4) & 31;
            int c8 = (i & 15) * 8;
            cpa16(base + 2 * ASZ + pl * BSZ + (r * RSB + c8) * 2,
                  Wt + pl * WNK + (size_t)(k0 + r) * N + bn + c8);
        }
    };

    float acc[2][8][4];
#pragma unroll
    for (int a = 0; a < 2; a++)
#pragma unroll
        for (int b = 0; b < 8; b++)
#pragma unroll
            for (int c = 0; c < 4; c++) acc[a][b][c] = 0.f;

    load_tile(0, 0);
    CPA_COMMIT;
    for (int c = 0; c < nc; c++) {
        if (c + 1 < nc) {
            load_tile((c + 1) & 1, c + 1);
            CPA_COMMIT;
            CPA_WAIT(1);
        } else {
            CPA_WAIT(0);
        }
        __syncthreads();
        uint32_t base = sb + (c & 1) * STG;

        uint32_t ah[2][2][4], al[2][2][4];
#pragma unroll
        for (int ks = 0; ks < 2; ks++)
#pragma unroll
            for (int mi = 0; mi < 2; mi++) {
                uint32_t ao = base + ((wm + mi * 16 + (l & 15)) * RSA + ks * 16 + (l >> 4) * 8) * 2;
                ldm_x4(ah[ks][mi], ao);
                ldm_x4(al[ks][mi], ao + ASZ);
            }
#pragma unroll
        for (int nf = 0; nf < 8; nf++) {
            uint32_t bo = base + 2 * ASZ +
                          ((((l >> 3) * 8) + (l & 7)) * RSB + wn + nf * 8) * 2;
            uint32_t bh[4], bl[4];
            ldm_x4_t(bh, bo);
            ldm_x4_t(bl, bo + BSZ);
#pragma unroll
            for (int ks = 0; ks < 2; ks++)
#pragma unroll
                for (int mi = 0; mi < 2; mi++) {
                    mma_bf16(acc[mi][nf], ah[ks][mi], bh + ks * 2);
                    mma_bf16(acc[mi][nf], ah[ks][mi], bl + ks * 2);
                    mma_bf16(acc[mi][nf], al[ks][mi], bh + ks * 2);
                }
        }
        __syncthreads();
    }

    int r0 = wm + (l >> 2);
    if (mode == 2) {
        float* tile  = (float*)sm;
        float* ps    = (float*)(sm + 66048);
        float* mus   = (float*)(sm + 68096);
        float* rstds = (float*)(sm + 68608);
#pragma unroll
        for (int mi = 0; mi < 2; mi++)
#pragma unroll
            for (int half = 0; half < 2; half++) {
                int row = r0 + mi * 16 + half * 8;
#pragma unroll
                for (int nf = 0; nf < 8; nf++) {
                    int col = wn + (l & 3) * 2 + nf * 8;
                    float v0 = acc[mi][nf][half * 2 + 0] + bias[col];
                    float v1 = acc[mi][nf][half * 2 + 1] + bias[col + 1];
                    size_t o = (size_t)(bm + row) * 128 + col;
                    v0 += res[o];
                    v1 += res[o + 1];
                    tile[row * 129 + col] = v0;
                    tile[row * 129 + col + 1] = v1;
                }
            }
        __syncthreads();
        {
            int row = tid & 127, hf = tid >> 7;
            float s = 0.f, q = 0.f;
#pragma unroll 8
            for (int c2 = 0; c2 < 64; c2++) {
                float v = tile[row * 129 + hf * 64 + c2];
                s += v;
                q += v * v;
            }
            ps[tid] = s;
            ps[256 + tid] = q;
        }
        __syncthreads();
        if (tid < 128) {
            float ss = ps[tid] + ps[tid + 128];
            float qq = ps[256 + tid] + ps[256 + tid + 128];
            float mu = ss * (1.0f / 128.0f);
            float var = qq * (1.0f / 128.0f) - mu * mu;
            mus[tid] = mu;
            rstds[tid] = rsqrtf(var + 1e-5f);
        }
        __syncthreads();
        for (int idx = tid; idx < 16384; idx += 256) {
            int r = idx >> 7, c2 = idx & 127;
            float val = (tile[r * 129 + c2] - mus[r]) * rstds[r] * lng[c2] + lnb[c2];
            size_t o = (size_t)(bm + r) * 128 + c2;
            C[o] = val;
            __nv_bfloat16 h, lo2;
            split_bf(val, h, lo2);
            Cbf[o] = h;
            Cbf[CMK + o] = lo2;
        }
        return;
    }

    int cb = bn + wn + (l & 3) * 2;
#pragma unroll
    for (int mi = 0; mi < 2; mi++) {
#pragma unroll
        for (int half = 0; half < 2; half++) {
            long long row = bm + r0 + mi * 16 + half * 8;
#pragma unroll
            for (int nf = 0; nf < 8; nf++) {
                int col = cb + nf * 8;
                float v0 = acc[mi][nf][half * 2 + 0];
                float v1 = acc[mi][nf][half * 2 + 1];
                if (bias) { v0 += bias[col]; v1 += bias[col + 1]; }
                size_t o = (size_t)row * N + col;
                if (mode == 1) {
                    __nv_bfloat16 h0, l0, h1, l1;
                    split_bf(v0, h0, l0);
                    split_bf(v1, h1, l1);
                    __nv_bfloat162 hh; hh.x = h0; hh.y = h1;
                    __nv_bfloat162 ll; ll.x = l0; ll.y = l1;
                    *(__nv_bfloat162*)(Cbf + o) = hh;
                    *(__nv_bfloat162*)(Cbf + CMK + o) = ll;
                } else {
                    if (res) { v0 += res[o]; v1 += res[o + 1]; }
                    *(float2*)(C + o) = make_float2(v0, v1);
                }
            }
        }
    }
}

// ---------------------------------------------------------------------------
// Stage-2 flash attention, double-buffered KV pipeline.
// smem: Q planes [0,20480); KV buffers [20480,61440) and [61440,102400);
// bias table at 102400.
// ---------------------------------------------------------------------------
#define FKV 20480
#define FBIAS 102400
#define FSMEM (102400 + 3969 * 4)

__global__ void __launch_bounds__(256)
flash2(const __nv_bfloat16* __restrict__ QKVbf, const float* __restrict__ table,
       __nv_bfloat16* __restrict__ Obf) {
    extern __shared__ char fsm[];
    uint32_t sb = smem_u32(fsm);
    float* sBias = (float*)(fsm + FBIAS);

    int tid = threadIdx.x, wid = tid >> 5, ln = tid & 31;
    int bh = blockIdx.y, b = bh >> 2, h = bh & 3;
    int bq = blockIdx.x * 128;
    const long long QMK = (long long)MTOK * 384;
    const long long OMK = (long long)MTOK * 128;
    long long tok0 = (long long)b * 1024;

    for (int i = tid; i < 3969; i += 256) sBias[i] = table[i * 4 + h];

    // Q planes (group 0)
#pragma unroll
    for (int i = tid; i < 1024; i += 256) {
        int pl = i >> 9, r = (i >> 2) & 127, c4 = (i & 3) * 8;
        cpa16(sb + pl * 10240 + (r * RSA + c4) * 2,
              QKVbf + pl * QMK + (tok0 + bq + r) * 384 + h * 32 + c4);
    }
    CPA_COMMIT;

    auto load_kv = [&](int kt) {
        uint32_t kbase = sb + FKV + (kt & 1) * 40960;
#pragma unroll
        for (int i = tid; i < 2048; i += 256) {
            int tensor = i >> 10;
            int pl = (i >> 9) & 1;
            int r = (i >> 2) & 127, c4 = (i & 3) * 8;
            cpa16(kbase + tensor * 20480 + pl * 10240 + (r * RSA + c4) * 2,
                  QKVbf + pl * QMK + (tok0 + kt * 128 + r) * 384 + 128 + tensor * 128 + h * 32 + c4);
        }
        CPA_COMMIT;
    };
    load_kv(0);
    CPA_WAIT(1);       // Q group complete
    __syncthreads();

    int rbase = wid * 16;
    uint32_t qh[2][4], ql[2][4];
#pragma unroll
    for (int ks = 0; ks < 2; ks++) {
        uint32_t ao = sb + ((rbase + (ln & 15)) * RSA + ks * 16 + (ln >> 4) * 8) * 2;
        ldm_x4(qh[ks], ao);
        ldm_x4(ql[ks], ao + 10240);
    }

    float oacc[4][4];
#pragma unroll
    for (int i = 0; i < 4; i++)
#pragma unroll
        for (int j = 0; j < 4; j++) oacc[i][j] = 0.f;
    float m0 = -1e30f, m1 = -1e30f, ls0 = 0.f, ls1 = 0.f;

    int n0 = bq + rbase + (ln >> 2);
    int n1 = n0 + 8;
    int i1a = n0 >> 5, j1a = n0 & 31;
    int i1b = n1 >> 5, j1b = n1 & 31;
    int mcb = 2 * (ln & 3);
    const float SC = 5.656854249492381f;

    for (int kt = 0; kt < 8; kt++) {
        if (kt + 1 < 8) {
            load_kv(kt + 1);
            CPA_WAIT(1);
        } else {
            CPA_WAIT(0);
        }
        __syncthreads();
        uint32_t kb = sb + FKV + (kt & 1) * 40960;

        float sa[16][4];
#pragma unroll
        for (int nf = 0; nf < 16; nf++) {
            sa[nf][0] = sa[nf][1] = sa[nf][2] = sa[nf][3] = 0.f;
            uint32_t bh4[4], bl4[4];
            uint32_t bo = kb + ((nf * 8 + (ln & 7)) * RSA + (ln >> 3) * 8) * 2;
            ldm_x4(bh4, bo);
            ldm_x4(bl4, bo + 10240);
            mma_bf16(sa[nf], qh[0], bh4 + 0);
            mma_bf16(sa[nf], qh[1], bh4 + 2);
            mma_bf16(sa[nf], qh[0], bl4 + 0);
            mma_bf16(sa[nf], qh[1], bl4 + 2);
            mma_bf16(sa[nf], ql[0], bh4 + 0);
            mma_bf16(sa[nf], ql[1], bh4 + 2);
        }

        float mx0 = -1e30f, mx1 = -1e30f;
#pragma unroll
        for (int nf = 0; nf < 16; nf++) {
            int mc = kt * 128 + nf * 8 + mcb;
            int i2a = mc >> 5, j2a = mc & 31;
            int i2b = (mc + 1) >> 5, j2b = (mc + 1) & 31;
            float s0 = sa[nf][0] * SC + sBias[(i1a - i2a + 31) * 63 + (j1a - j2a + 31)];
            float s1 = sa[nf][1] * SC + sBias[(i1a - i2b + 31) * 63 + (j1a - j2b + 31)];
            float s2 = sa[nf][2] * SC + sBias[(i1b - i2a + 31) * 63 + (j1b - j2a + 31)];
            float s3 = sa[nf][3] * SC + sBias[(i1b - i2b + 31) * 63 + (j1b - j2b + 31)];
            sa[nf][0] = s0; sa[nf][1] = s1; sa[nf][2] = s2; sa[nf][3] = s3;
            mx0 = fmaxf(mx0, fmaxf(s0, s1));
            mx1 = fmaxf(mx1, fmaxf(s2, s3));
        }
        mx0 = fmaxf(mx0, __shfl_xor_sync(0xffffffffu, mx0, 1));
        mx0 = fmaxf(mx0, __shfl_xor_sync(0xffffffffu, mx0, 2));
        mx1 = fmaxf(mx1, __shfl_xor_sync(0xffffffffu, mx1, 1));
        mx1 = fmaxf(mx1, __shfl_xor_sync(0xffffffffu, mx1, 2));
        float mn0 = fmaxf(m0, mx0), mn1 = fmaxf(m1, mx1);
        float f0 = __expf(m0 - mn0), f1 = __expf(m1 - mn1);

        float su0 = 0.f, su1 = 0.f;
#pragma unroll
        for (int nf = 0; nf < 16; nf++) {
            float p0 = __expf(sa[nf][0] - mn0);
            float p1 = __expf(sa[nf][1] - mn0);
            float p2 = __expf(sa[nf][2] - mn1);
            float p3 = __expf(sa[nf][3] - mn1);
            sa[nf][0] = p0; sa[nf][1] = p1; sa[nf][2] = p2; sa[nf][3] = p3;
            su0 += p0 + p1; su1 += p2 + p3;
        }
        su0 += __shfl_xor_sync(0xffffffffu, su0, 1);
        su0 += __shfl_xor_sync(0xffffffffu, su0, 2);
        su1 += __shfl_xor_sync(0xffffffffu, su1, 1);
        su1 += __shfl_xor_sync(0xffffffffu, su1, 2);
        ls0 = ls0 * f0 + su0;
        ls1 = ls1 * f1 + su1;
        m0 = mn0; m1 = mn1;

#pragma unroll
        for (int nd = 0; nd < 4; nd++) {
            oacc[nd][0] *= f0; oacc[nd][1] *= f0;
            oacc[nd][2] *= f1; oacc[nd][3] *= f1;
        }

#pragma unroll
        for (int ks2 = 0; ks2 < 4; ks2++) {
            int k0 = ks2 * 32;
            uint32_t pa0h[4], pa0l[4], pa1h[4], pa1l[4];
            int nfa = 4 * ks2, nfb = nfa + 1, nfc = nfa + 2, nfd = nfa + 3;
            pa0h[0] = pack_hi(sa[nfa][0], sa[nfa][1]);
            pa0h[1] = pack_hi(sa[nfa][2], sa[nfa][3]);
            pa0h[2] = pack_hi(sa[nfb][0], sa[nfb][1]);
            pa0h[3] = pack_hi(sa[nfb][2], sa[nfb][3]);
            pa0l[0] = pack_lo(sa[nfa][0], sa[nfa][1]);
            pa0l[1] = pack_lo(sa[nfa][2], sa[nfa][3]);
            pa0l[2] = pack_lo(sa[nfb][0], sa[nfb][1]);
            pa0l[3] = pack_lo(sa[nfb][2], sa[nfb][3]);
            pa1h[0] = pack_hi(sa[nfc][0], sa[nfc][1]);
            pa1h[1] = pack_hi(sa[nfc][2], sa[nfc][3]);
            pa1h[2] = pack_hi(sa[nfd][0], sa[nfd][1]);
            pa1h[3] = pack_hi(sa[nfd][2], sa[nfd][3]);
            pa1l[0] = pack_lo(sa[nfc][0], sa[nfc][1]);
            pa1l[1] = pack_lo(sa[nfc][2], sa[nfc][3]);
            pa1l[2] = pack_lo(sa[nfd][0], sa[nfd][1]);
            pa1l[3] = pack_lo(sa[nfd][2], sa[nfd][3]);
#pragma unroll
            for (int nd = 0; nd < 4; nd++) {
                uint32_t vh4[4], vl4[4];
                uint32_t vo = kb + 20480 + ((k0 + (ln >> 3) * 8 + (ln & 7)) * RSA + nd * 8) * 2;
                ldm_x4_t(vh4, vo);
                ldm_x4_t(vl4, vo + 10240);
                mma_bf16(oacc[nd], pa0h, vh4 + 0);
                mma_bf16(oacc[nd], pa1h, vh4 + 2);
                mma_bf16(oacc[nd], pa0h, vl4 + 0);
                mma_bf16(oacc[nd], pa1h, vl4 + 2);
                mma_bf16(oacc[nd], pa0l, vh4 + 0);
                mma_bf16(oacc[nd], pa1l, vh4 + 2);
            }
        }
        __syncthreads();
    }

    float inv0 = 1.0f / ls0, inv1 = 1.0f / ls1;
    size_t o0 = (size_t)(tok0 + n0) * 128 + h * 32;
    size_t o1 = (size_t)(tok0 + n1) * 128 + h * 32;
#pragma unroll
    for (int nd = 0; nd < 4; nd++) {
        int d = nd * 8 + mcb;
        float a0 = oacc[nd][0] * inv0, a1 = oacc[nd][1] * inv0;
        float b0 = oacc[nd][2] * inv1, b1 = oacc[nd][3] * inv1;
        __nv_bfloat16 h0, l0, h1, l1;
        split_bf(a0, h0, l0); split_bf(a1, h1, l1);
        __nv_bfloat162 hh; hh.x = h0; hh.y = h1;
        __nv_bfloat162 ll; ll.x = l0; ll.y = l1;
        *(__nv_bfloat162*)(Obf + o0 + d) = hh;
        *(__nv_bfloat162*)(Obf + OMK + o0 + d) = ll;
        split_bf(b0, h0, l0); split_bf(b1, h1, l1);
        hh.x = h0; hh.y = h1; ll.x = l0; ll.y = l1;
        *(__nv_bfloat162*)(Obf + o1 + d) = hh;
        *(__nv_bfloat162*)(Obf + OMK + o1 + d) = ll;
    }
}

// ---------------------------------------------------------------------------
// Stage-1 attention on tensor cores (unchanged from R5).
// ---------------------------------------------------------------------------
#define ASQ 0
#define ASK 10240
#define ASV 20480
#define ASB 30720

__global__ void __launch_bounds__(128)
attn_small_tc(const __nv_bfloat16* __restrict__ QKVbf, const float* __restrict__ table,
              __nv_bfloat16* __restrict__ Obf) {
    __shared__ __align__(16) char sm1[31424];
    uint32_t sb = smem_u32(sm1);
    float* sT = (float*)(sm1 + ASB);

    int tid = threadIdx.x, wid = tid >> 5, ln = tid & 31;
    int bh = blockIdx.x, b = bh >> 2, h = bh & 3;
    const long long QMK = (long long)MTOK * 384;
    const long long OMK = (long long)MTOK * 128;
    long long tokb = (long long)b * 49;

    for (int i = tid; i < 169; i += 128) sT[i] = table[i * 4 + h];
#pragma unroll
    for (int i = tid; i < 1536; i += 128) {
        int tensor = i / 512;
        int pl = (i >> 8) & 1;
        int r = (i >> 2) & 63;
        int c4 = (i & 3) * 8;
        int rc = r < 49 ? r : 48;
        cpa16(sb + tensor * 10240 + pl * 5120 + (r * RSA + c4) * 2,
              QKVbf + pl * QMK + (tokb + rc) * 384 + tensor * 128 + h * 32 + c4);
    }
    CPA_COMMIT;
    CPA_WAIT(0);
    __syncthreads();

    uint32_t qh[2][4], ql[2][4];
#pragma unroll
    for (int ks = 0; ks < 2; ks++) {
        uint32_t ao = sb + ASQ + ((wid * 16 + (ln & 15)) * RSA + ks * 16 + (ln >> 4) * 8) * 2;
        ldm_x4(qh[ks], ao);
        ldm_x4(ql[ks], ao + 5120);
    }

    float sa[8][4];
#pragma unroll
    for (int nf = 0; nf < 8; nf++) {
        sa[nf][0] = sa[nf][1] = sa[nf][2] = sa[nf][3] = 0.f;
        uint32_t bh4[4], bl4[4];
        uint32_t bo = sb + ASK + ((nf * 8 + (ln & 7)) * RSA + (ln >> 3) * 8) * 2;
        ldm_x4(bh4, bo);
        ldm_x4(bl4, bo + 5120);
        mma_bf16(sa[nf], qh[0], bh4 + 0);
        mma_bf16(sa[nf], qh[1], bh4 + 2);
        mma_bf16(sa[nf], qh[0], bl4 + 0);
        mma_bf16(sa[nf], qh[1], bl4 + 2);
        mma_bf16(sa[nf], ql[0], bh4 + 0);
        mma_bf16(sa[nf], ql[1], bh4 + 2);
    }

    int n0 = wid * 16 + (ln >> 2);
    int n1 = n0 + 8;
    int n0c = n0 < 49 ? n0 : 48;
    int n1c = n1 < 49 ? n1 : 48;
    int i1a = n0c / 7, j1a = n0c % 7;
    int i1b = n1c / 7, j1b = n1c % 7;
    int mcb = 2 * (ln & 3);
    const float SC = 5.656854249492381f;

    float mx0 = -1e30f, mx1 = -1e30f;
#pragma unroll
    for (int nf = 0; nf < 8; nf++) {
        int mc = nf * 8 + mcb;
        float s0, s1, s2, s3;
        if (mc < 49) {
            int i2 = mc / 7, j2 = mc % 7;
            s0 = sa[nf][0] * SC + sT[(i1a - i2 + 6) * 13 + (j1a - j2 + 6)];
            s2 = sa[nf][2] * SC + sT[(i1b - i2 + 6) * 13 + (j1b - j2 + 6)];
        } else { s0 = -1e30f; s2 = -1e30f; }
        if (mc + 1 < 49) {
            int i2 = (mc + 1) / 7, j2 = (mc + 1) % 7;
            s1 = sa[nf][1] * SC + sT[(i1a - i2 + 6) * 13 + (j1a - j2 + 6)];
            s3 = sa[nf][3] * SC + sT[(i1b - i2 + 6) * 13 + (j1b - j2 + 6)];
        } else { s1 = -1e30f; s3 = -1e30f; }
        sa[nf][0] = s0; sa[nf][1] = s1; sa[nf][2] = s2; sa[nf][3] = s3;
        mx0 = fmaxf(mx0, fmaxf(s0, s1));
        mx1 = fmaxf(mx1, fmaxf(s2, s3));
    }
    mx0 = fmaxf(mx0, __shfl_xor_sync(0xffffffffu, mx0, 1));
    mx0 = fmaxf(mx0, __shfl_xor_sync(0xffffffffu, mx0, 2));
    mx1 = fmaxf(mx1, __shfl_xor_sync(0xffffffffu, mx1, 1));
    mx1 = fmaxf(mx1, __shfl_xor_sync(0xffffffffu, mx1, 2));

    float ls0 = 0.f, ls1 = 0.f;
#pragma unroll
    for (int nf = 0; nf < 8; nf++) {
        float p0 = __expf(sa[nf][0] - mx0);
        float p1 = __expf(sa[nf][1] - mx0);
        float p2 = __expf(sa[nf][2] - mx1);
        float p3 = __expf(sa[nf][3] - mx1);
        sa[nf][0] = p0; sa[nf][1] = p1; sa[nf][2] = p2; sa[nf][3] = p3;
        ls0 += p0 + p1; ls1 += p2 + p3;
    }
    ls0 += __shfl_xor_sync(0xffffffffu, ls0, 1);
    ls0 += __shfl_xor_sync(0xffffffffu, ls0, 2);
    ls1 += __shfl_xor_sync(0xffffffffu, ls1, 1);
    ls1 += __shfl_xor_sync(0xffffffffu, ls1, 2);

    float oacc[4][4];
#pragma unroll
    for (int i = 0; i < 4; i++)
#pragma unroll
        for (int j = 0; j < 4; j++) oacc[i][j] = 0.f;
#pragma unroll
    for (int ks2 = 0; ks2 < 2; ks2++) {
        int k0 = ks2 * 32;
        uint32_t pa0h[4], pa0l[4], pa1h[4], pa1l[4];
        int nfa = 4 * ks2, nfb = nfa + 1, nfc = nfa + 2, nfd = nfa + 3;
        pa0h[0] = pack_hi(sa[nfa][0], sa[nfa][1]);
        pa0h[1] = pack_hi(sa[nfa][2], sa[nfa][3]);
        pa0h[2] = pack_hi(sa[nfb][0], sa[nfb][1]);
        pa0h[3] = pack_hi(sa[nfb][2], sa[nfb][3]);
        pa0l[0] = pack_lo(sa[nfa][0], sa[nfa][1]);
        pa0l[1] = pack_lo(sa[nfa][2], sa[nfa][3]);
        pa0l[2] = pack_lo(sa[nfb][0], sa[nfb][1]);
        pa0l[3] = pack_lo(sa[nfb][2], sa[nfb][3]);
        pa1h[0] = pack_hi(sa[nfc][0], sa[nfc][1]);
        pa1h[1] = pack_hi(sa[nfc][2], sa[nfc][3]);
        pa1h[2] = pack_hi(sa[nfd][0], sa[nfd][1]);
        pa1h[3] = pack_hi(sa[nfd][2], sa[nfd][3]);
        pa1l[0] = pack_lo(sa[nfc][0], sa[nfc][1]);
        pa1l[1] = pack_lo(sa[nfc][2], sa[nfc][3]);
        pa1l[2] = pack_lo(sa[nfd][0], sa[nfd][1]);
        pa1l[3] = pack_lo(sa[nfd][2], sa[nfd][3]);
#pragma unroll
        for (int nd = 0; nd < 4; nd++) {
            uint32_t vh4[4], vl4[4];
            uint32_t vo = sb + ASV + ((k0 + (ln >> 3) * 8 + (ln & 7)) * RSA + nd * 8) * 2;
            ldm_x4_t(vh4, vo);
            ldm_x4_t(vl4, vo + 5120);
            mma_bf16(oacc[nd], pa0h, vh4 + 0);
            mma_bf16(oacc[nd], pa1h, vh4 + 2);
            mma_bf16(oacc[nd], pa0h, vl4 + 0);
            mma_bf16(oacc[nd], pa1h, vl4 + 2);
            mma_bf16(oacc[nd], pa0l, vh4 + 0);
            mma_bf16(oacc[nd], pa1l, vh4 + 2);
        }
    }

    float inv0 = 1.0f / ls0, inv1 = 1.0f / ls1;
#pragma unroll
    for (int nd = 0; nd < 4; nd++) {
        int d = nd * 8 + mcb;
        if (n0 < 49) {
            size_t o0 = (size_t)(tokb + n0) * 128 + h * 32 + d;
            __nv_bfloat16 h0, l0, h1, l1;
            split_bf(oacc[nd][0] * inv0, h0, l0);
            split_bf(oacc[nd][1] * inv0, h1, l1);
            __nv_bfloat162 hh; hh.x = h0; hh.y = h1;
            __nv_bfloat162 ll; ll.x = l0; ll.y = l1;
            *(__nv_bfloat162*)(Obf + o0) = hh;
            *(__nv_bfloat162*)(Obf + OMK + o0) = ll;
        }
        if (n1 < 49) {
            size_t o1 = (size_t)(tokb + n1) * 128 + h * 32 + d;
            __nv_bfloat16 h0, l0, h1, l1;
            split_bf(oacc[nd][2] * inv1, h0, l0);
            split_bf(oacc[nd][3] * inv1, h1, l1);
            __nv_bfloat162 hh; hh.x = h0; hh.y = h1;
            __nv_bfloat162 ll; ll.x = l0; ll.y = l1;
            *(__nv_bfloat162*)(Obf + o1) = hh;
            *(__nv_bfloat162*)(Obf + OMK + o1) = ll;
        }
    }
}

// ------------------------- permutations ------------------------------------
__global__ void __launch_bounds__(256)
winpart_tile(const float* __restrict__ x, float* __restrict__ X,
             __nv_bfloat16* __restrict__ Xbf) {
    __shared__ float tile[32][65];
    const long long XMK = (long long)MTOK * 128;
    int sp0 = blockIdx.x * 64;
    int c0 = blockIdx.y * 32;
    int tid = threadIdx.x;
    {
        int ci = tid >> 3, si = (tid & 7) * 8;
        const float* p = x + (size_t)(c0 + ci) * MTOK + sp0 + si;
        float4 u0 = *(const float4*)p;
        float4 u1 = *(const float4*)(p + 4);
        tile[ci][si + 0] = u0.x; tile[ci][si + 1] = u0.y;
        tile[ci][si + 2] = u0.z; tile[ci][si + 3] = u0.w;
        tile[ci][si + 4] = u1.x; tile[ci][si + 5] = u1.y;
        tile[ci][si + 6] = u1.z; tile[ci][si + 7] = u1.w;
    }
    __syncthreads();
    {
        int si = tid >> 2, cj = (tid & 3) * 8;
        int sp = sp0 + si;
        int hh = sp / HWDIM, ww = sp % HWDIM;
        int out_t = ((hh / 7) * 32 + (ww / 7)) * 49 + (hh % 7) * 7 + (ww % 7);
        size_t ob = (size_t)out_t * 128 + c0 + cj;
#pragma unroll
        for (int k = 0; k < 8; k++) {
            float v = tile[cj + k][si];
            X[ob + k] = v;
            __nv_bfloat16 h, l;
            split_bf(v, h, l);
            Xbf[ob + k] = h;
            Xbf[XMK + ob + k] = l;
        }
    }
}

// b2g permute, coalesced both sides via 32x128 smem tile transpose.
// Block (ho, tok1): reads A[((ho*32+wo)*49+tok1)*128 + c] (c fast, coalesced),
// writes runs of 32 consecutive dest elements (wo fast).
__global__ void __launch_bounds__(256)
permute_b2g_tile(const float* __restrict__ A, float* __restrict__ Xg,
                 __nv_bfloat16* __restrict__ Xbf) {
    __shared__ float tile[32][129];
    const long long XMK = (long long)MTOK * 128;
    int ho = blockIdx.x;
    int tok1 = blockIdx.y;
    int hi2 = tok1 / 7, wi2 = tok1 % 7;
    int tid = threadIdx.x;
    for (int i = tid; i < 1024; i += 256) {
        int wo = i >> 5, c4 = (i & 31) * 4;
        float4 u = *(const float4*)(A + ((size_t)((ho * 32 + wo) * 49 + tok1)) * 128 + c4);
        tile[wo][c4 + 0] = u.x; tile[wo][c4 + 1] = u.y;
        tile[wo][c4 + 2] = u.z; tile[wo][c4 + 3] = u.w;
    }
    __syncthreads();
    for (int i = tid; i < 1024; i += 256) {
        int c = i & 127, w4 = (i >> 7) * 4;
        int f = (((c * 32 + ho) * 7 + hi2) * 7 + wi2) * 32;
        int cg = f & 127, s = f >> 7;
        int h2 = s / 224, w2 = s % 224;
        int dtok = ((h2 >> 5) * 7 + (w2 >> 5)) * 1024 + (h2 & 31) * 32 + (w2 & 31);
        size_t d0 = (size_t)dtok * 128 + cg + w4;
        float v0 = tile[w4 + 0][c], v1 = tile[w4 + 1][c];
        float v2 = tile[w4 + 2][c], v3 = tile[w4 + 3][c];
        *(float4*)(Xg + d0) = make_float4(v0, v1, v2, v3);
        uint2 ph, pl2;
        ph.x = pack_hi(v0, v1); ph.y = pack_hi(v2, v3);
        pl2.x = pack_lo(v0, v1); pl2.y = pack_lo(v2, v3);
        *(uint2*)(Xbf + d0) = ph;
        *(uint2*)(Xbf + XMK + d0) = pl2;
    }
}

// g2out, vectorized x4 on the (coalesced) output side.
__global__ void permute_g2out_kernel(const float* __restrict__ A, float* __restrict__ out) {
    int idx = (blockIdx.x * 256 + threadIdx.x) * 4;
    if (idx >= MTOK * CCH) return;
    float4 r;
    float* rp = (float*)&r;
#pragma unroll
    for (int k = 0; k < 4; k++) {
        int id = idx + k;
        int w2 = id % HWDIM;
        int t = id / HWDIM;
        int h2 = t % HWDIM;
        int c2 = t / HWDIM;
        int f = (h2 * HWDIM + w2) * CCH + c2;
        int gwo = f % 7;  f /= 7;
        int gwi = f & 31; f >>= 5;
        int ghi = f & 31; f >>= 5;
        int gho = f % 7;  f /= 7;
        int c = f;
        rp[k] = A[((size_t)((gho * 7 + gwo) * 1024 + ghi * 32 + gwi)) * 128 + c];
    }
    *(float4*)(out + idx) = r;
}

// ------------------------- weight pre-split ---------------------------------
struct WParams {
    const float* src[8];
    __nv_bfloat16* dst[8];
    int N[8];
    int K[8];
};
__global__ void convw8(WParams p) {
    int w = blockIdx.y;
    int N = p.N[w], K = p.K[w];
    int NK = N * K;
    const float* src = p.src[w];
    __nv_bfloat16* dst = p.dst[w];
    for (int idx = blockIdx.x * 256 + threadIdx.x; idx < NK; idx += gridDim.x * 256) {
        int n = idx / K, k = idx % K;
        float v = src[idx];
        __nv_bfloat16 h, l;
        split_bf(v, h, l);
        dst[(size_t)k * N + n] = h;
        dst[(size_t)NK + (size_t)k * N + n] = l;
    }
}

// ------------------------- host orchestration -------------------------------
extern "C" void kernel_launch(void* const* d_in, const int* in_sizes, int n_in,
                              void* d_out, int out_size) {
    const float* x = (const float*)d_in[0];
    const float* bp[10];
    const float* gp[10];
    for (int i = 0; i < 10; i++) bp[i] = (const float*)d_in[1 + i];
    for (int i = 0; i < 10; i++) gp[i] = (const float*)d_in[11 + i];

    cudaFuncSetAttribute(gemm_bf, cudaFuncAttributeMaxDynamicSharedMemorySize, GSMEM);
    cudaFuncSetAttribute(flash2, cudaFuncAttributeMaxDynamicSharedMemorySize, FSMEM);

    float *X, *Yn, *Out;
    __nv_bfloat16 *Xbf, *QKVbf, *Obf, *Ynbf, *Zbf, *Wbf;
    cudaGetSymbolAddress((void**)&X, g_X);
    cudaGetSymbolAddress((void**)&Yn, g_Yn);
    cudaGetSymbolAddress((void**)&Out, g_Out);
    cudaGetSymbolAddress((void**)&Xbf, g_Xbf);
    cudaGetSymbolAddress((void**)&QKVbf, g_QKVbf);
    cudaGetSymbolAddress((void**)&Obf, g_Obf);
    cudaGetSymbolAddress((void**)&Ynbf, g_Ynbf);
    cudaGetSymbolAddress((void**)&Zbf, g_Zbf);
    cudaGetSymbolAddress((void**)&Wbf, g_Wbf);

    const long long XMK = (long long)MTOK * 128;
    const long long QMK = (long long)MTOK * 384;
    const long long ZMK = (long long)MTOK * 512;

    WParams wp;
    wp.src[0] = bp[1]; wp.dst[0] = Wbf + 0;      wp.N[0] = 384; wp.K[0] = 128;
    wp.src[1] = bp[2]; wp.dst[1] = Wbf + 98304;  wp.N[1] = 128; wp.K[1] = 128;
    wp.src[2] = bp[6]; wp.dst[2] = Wbf + 131072; wp.N[2] = 512; wp.K[2] = 128;
    wp.src[3] = bp[8]; wp.dst[3] = Wbf + 262144; wp.N[3] = 128; wp.K[3] = 512;
    wp.src[4] = gp[1]; wp.dst[4] = Wbf + 393216; wp.N[4] = 384; wp.K[4] = 128;
    wp.src[5] = gp[2]; wp.dst[5] = Wbf + 491520; wp.N[5] = 128; wp.K[5] = 128;
    wp.src[6] = gp[6]; wp.dst[6] = Wbf + 524288; wp.N[6] = 512; wp.K[6] = 128;
    wp.src[7] = gp[8]; wp.dst[7] = Wbf + 655360; wp.N[7] = 128; wp.K[7] = 512;
    convw8<<<dim3(64, 8), 256>>>(wp);

    // ================= Stage 1: 7x7 windows ==================
    winpart_tile<<<dim3(MTOK / 64, 4), 256>>>(x, X, Xbf);
    gemm_bf<<<dim3(392, 3), 256, GSMEM>>>(Xbf, XMK, Wbf + 0, 49152, 128, 384,
                                          nullptr, nullptr, nullptr, QKVbf, QMK, 1, nullptr, nullptr);
    attn_small_tc<<<4096, 128>>>(QKVbf, bp[0], Obf);
    gemm_bf<<<dim3(392, 1), 256, GSMEM>>>(Obf, XMK, Wbf + 98304, 16384, 128, 128,
                                          bp[3], X, Yn, Ynbf, XMK, 2, bp[4], bp[5]);
    gemm_bf<<<dim3(392, 4), 256, GSMEM>>>(Ynbf, XMK, Wbf + 131072, 65536, 128, 512,
                                          bp[7], nullptr, nullptr, Zbf, ZMK, 1, nullptr, nullptr);
    gemm_bf<<<dim3(392, 1), 256, GSMEM>>>(Zbf, ZMK, Wbf + 262144, 65536, 512, 128,
                                          bp[9], Yn, Out, nullptr, 0, 0, nullptr, nullptr);

    permute_b2g_tile<<<dim3(32, 49), 256>>>(Out, X, Xbf);

    // ================= Stage 2: 32x32 grid ===================
    gemm_bf<<<dim3(392, 3), 256, GSMEM>>>(Xbf, XMK, Wbf + 393216, 49152, 128, 384,
                                          nullptr, nullptr, nullptr, QKVbf, QMK, 1, nullptr, nullptr);
    flash2<<<dim3(8, 196), 256, FSMEM>>>(QKVbf, gp[0], Obf);
    gemm_bf<<<dim3(392, 1), 256, GSMEM>>>(Obf, XMK, Wbf + 491520, 16384, 128, 128,
                                          gp[3], X, Yn, Ynbf, XMK, 2, gp[4], gp[5]);
    gemm_bf<<<dim3(392, 4), 256, GSMEM>>>(Ynbf, XMK, Wbf + 524288, 65536, 128, 512,
                                          gp[7], nullptr, nullptr, Zbf, ZMK, 1, nullptr, nullptr);
    gemm_bf<<<dim3(392, 1), 256, GSMEM>>>(Zbf, ZMK, Wbf + 655360, 65536, 512, 128,
                                          gp[9], Yn, Out, nullptr, 0, 0, nullptr, nullptr);

    permute_g2out_kernel<<<MTOK * CCH / 1024, 256>>>(Out, (float*)d_out);
}